// round 1
// baseline (speedup 1.0000x reference)
#include <cuda_runtime.h>
#include <cstdint>

// ---------------- problem constants ----------------
#define B_   16
#define CIN  512
#define COUT 512
#define HS   36          // source spatial
#define HO   38          // conv output spatial (pad=2, k=3)
#define HP   40          // padded input spatial
#define NPIX (HO*HO)     // 1444
#define NOUT (HS*HS)     // 1296

// ---------------- device scratch (no mallocs allowed) ----------------
__device__ float g_sn[B_*CIN];            // per-sample normalized styles
__device__ float g_bmod[B_*COUT];         // modulated bias
__device__ float g_r[COUT];               // rsqrt(mean(weight^2)) per out channel
__device__ float g_S2t[CIN*COUT];         // sum_k weight^2, layout [i][o]
__device__ float g_outscale[B_*COUT];     // r*d*input_gain
__device__ float g_wt[CIN*9*COUT];        // transposed weight, layout [(i*9+k)][o]
__device__ float g_xpad[(size_t)B_*CIN*HP*HP];   // x * sn, zero-padded by 2
__device__ float g_conv[(size_t)B_*COUT*NPIX];   // conv output + bias

// ---------------- K0: styles, style-norm, modulated bias ----------------
// one block per sample, 512 threads (thread = channel index)
__global__ void k_style(const float* __restrict__ w, const float* __restrict__ msg,
                        const float* __restrict__ aw, const float* __restrict__ ab,
                        const float* __restrict__ ms, const float* __restrict__ mb,
                        const float* __restrict__ bias)
{
    int b = blockIdx.x;
    int i = threadIdx.x;                  // 0..511
    __shared__ float sw[512];
    __shared__ float sm[64];
    __shared__ float red[512];

    sw[i] = w[b*512 + i];
    if (i < 64) sm[i] = msg[b*64 + i];
    __syncthreads();

    // styles[b,i] = sum_j w[b,j]*aw[i,j] + ab[i]
    float acc = ab[i];
    const float4* awr = (const float4*)(aw + (size_t)i*512);
    #pragma unroll 4
    for (int j4 = 0; j4 < 128; j4++) {
        float4 a = awr[j4];
        acc += sw[4*j4+0]*a.x + sw[4*j4+1]*a.y + sw[4*j4+2]*a.z + sw[4*j4+3]*a.w;
    }
    // + 0.01 * msg @ map_style_w   (ms layout [m][i], coalesced over i)
    float macc = 0.f;
    #pragma unroll 8
    for (int m = 0; m < 64; m++) macc += sm[m]*ms[m*512 + i];
    acc += 0.01f*macc;

    // sn = s * rsqrt(mean(s^2 over i))
    red[i] = acc*acc;
    __syncthreads();
    for (int s = 256; s > 0; s >>= 1) {
        if (i < s) red[i] += red[i+s];
        __syncthreads();
    }
    g_sn[b*512+i] = acc * rsqrtf(red[0]*(1.0f/512.0f));

    // modulated bias (o = i): b = bias + 0.01 * msg @ map_bias_w
    float bacc = 0.f;
    #pragma unroll 8
    for (int m = 0; m < 64; m++) bacc += sm[m]*mb[m*512 + i];
    g_bmod[b*512+i] = bias[i] + 0.01f*bacc;
}

// ---------------- K1: weight stats + transpose ----------------
// one block per out channel o
__global__ void k_wstats(const float* __restrict__ weight)
{
    int o = blockIdx.x;
    int tid = threadIdx.x;                // 256
    __shared__ float red[256];
    float part = 0.f;
    for (int i = tid; i < 512; i += 256) {
        const float* wp = weight + ((size_t)o*512 + i)*9;
        float s2 = 0.f;
        #pragma unroll
        for (int k = 0; k < 9; k++) {
            float v = wp[k];
            s2 += v*v;
            g_wt[(size_t)(i*9+k)*512 + o] = v;     // [i*9+k][o]
        }
        g_S2t[i*512 + o] = s2;
        part += s2;
    }
    red[tid] = part;
    __syncthreads();
    for (int s = 128; s > 0; s >>= 1) { if (tid < s) red[tid] += red[tid+s]; __syncthreads(); }
    if (tid == 0) g_r[o] = rsqrtf(red[0]*(1.0f/4608.0f));
}

// ---------------- K2: demod scale ----------------
// grid (4, 16), 128 threads: thread handles one (b,o)
__global__ void k_outscale(const float* __restrict__ ema)
{
    int b = blockIdx.y;
    int o = blockIdx.x*128 + threadIdx.x;
    __shared__ float ssn2[512];
    for (int i = threadIdx.x; i < 512; i += 128) { float v = g_sn[b*512+i]; ssn2[i] = v*v; }
    __syncthreads();
    float acc = 0.f;
    #pragma unroll 4
    for (int i = 0; i < 512; i++) acc += ssn2[i]*g_S2t[i*512 + o];
    float r = g_r[o];
    float d = rsqrtf(r*r*acc + 1e-8f);
    g_outscale[b*512+o] = r*d*rsqrtf(ema[0]);
}

// ---------------- K3: modulate + pad input ----------------
__global__ void k_xpad(const float* __restrict__ x)
{
    int idx = blockIdx.x*256 + threadIdx.x;
    if (idx >= B_*CIN*HP*HP) return;
    int c = idx % HP;
    int t = idx / HP;
    int r = t % HP; t /= HP;
    int i = t % CIN; int b = t / CIN;
    float v = 0.f;
    if (r >= 2 && r < 38 && c >= 2 && c < 38)
        v = x[((size_t)(b*CIN+i)*HS + (r-2))*HS + (c-2)] * g_sn[b*CIN+i];
    g_xpad[idx] = v;
}

// ---------------- K4: shared-weight 3x3 conv (the hot kernel) ----------------
// grid (12 pixel-tiles, 4 cout-tiles, 16 samples), 256 threads.
// Tile: 128 Cout x 128 flattened pixels; 8x8 register micro-tile per thread.
// Pixel interleave stride 16 -> SMEM X loads are consecutive across the warp.
__global__ void __launch_bounds__(256, 2) k_conv()
{
    const int b  = blockIdx.z;
    const int o0 = blockIdx.y * 128;
    const int p0 = blockIdx.x * 128;
    const int tid = threadIdx.x;
    const int og = tid >> 4;              // 0..15 (cout group of 8)
    const int pg = tid & 15;              // 0..15 (pixel lane)

    __shared__ float sW[8*9*128];         // [ic][tap][o]   36.0 KB
    __shared__ float sX[8][7][40];        // [ic][row][col]  8.75 KB

    int prow[8], pcol[8];
    #pragma unroll
    for (int j = 0; j < 8; j++) {
        int p = p0 + pg + j*16;           // up to 1535 (masked at store)
        int r = p / 38;
        prow[j] = r;
        pcol[j] = p - r*38;
    }
    const int r0 = p0 / 38;               // 7 input rows cover the whole tile

    float acc[8][8];
    #pragma unroll
    for (int i = 0; i < 8; i++)
        #pragma unroll
        for (int j = 0; j < 8; j++) acc[i][j] = 0.f;

    const float* xb = g_xpad + (size_t)b*CIN*HP*HP;

    for (int ic0 = 0; ic0 < 512; ic0 += 8) {
        // weight tile: coalesced from transposed layout
        for (int e = tid; e < 8*9*128; e += 256) {
            int oo = e & 127;
            int kk = e >> 7;              // ic*9+k  (0..71)
            sW[e] = g_wt[(size_t)(ic0*9 + kk)*512 + o0 + oo];
        }
        // input tile: 8 ch x 7 rows x 40 cols
        for (int e = tid; e < 8*7*40; e += 256) {
            int col = e % 40;
            int t2  = e / 40;
            int rr  = t2 % 7;
            int ic  = t2 / 7;
            int grow = r0 + rr;
            float v = 0.f;
            if (grow < 40) v = xb[((size_t)(ic0+ic)*40 + grow)*40 + col];
            sX[ic][rr][col] = v;
        }
        __syncthreads();

        #pragma unroll 2
        for (int ic = 0; ic < 8; ic++) {
            #pragma unroll
            for (int dy = 0; dy < 3; dy++) {
                #pragma unroll
                for (int dx = 0; dx < 3; dx++) {
                    float wv[8];
                    const float* wp = &sW[((ic*9 + dy*3 + dx) << 7) + og*8];
                    #pragma unroll
                    for (int i = 0; i < 8; i++) wv[i] = wp[i];
                    float xv[8];
                    #pragma unroll
                    for (int j = 0; j < 8; j++)
                        xv[j] = sX[ic][prow[j]-r0+dy][pcol[j]+dx];
                    #pragma unroll
                    for (int i = 0; i < 8; i++)
                        #pragma unroll
                        for (int j = 0; j < 8; j++)
                            acc[i][j] += wv[i]*xv[j];
                }
            }
        }
        __syncthreads();
    }

    // epilogue: demod scale + modulated bias
    #pragma unroll
    for (int i = 0; i < 8; i++) {
        int o = o0 + og*8 + i;
        float sc = g_outscale[b*512 + o];
        float bb = g_bmod[b*512 + o];
        #pragma unroll
        for (int j = 0; j < 8; j++) {
            int p = p0 + pg + j*16;
            if (p < NPIX) g_conv[((size_t)b*COUT + o)*NPIX + p] = acc[i][j]*sc + bb;
        }
    }
}

// ---------------- K5: fused filtered_lrelu (up-FIR -> act -> down-FIR) ----------------
// one block per (b,o) plane; everything stays in SMEM (aliased regions, 46.8 KB)
__global__ void k_fir(const float* __restrict__ fu, const float* __restrict__ fd,
                      float* __restrict__ out)
{
    int plane = blockIdx.x;               // b*512 + o
    const float* src = g_conv + (size_t)plane*NPIX;
    float* dst = out + (size_t)plane*NOUT;

    __shared__ float smem[11688];
    __shared__ float fuf[12], fdf[12];
    float* sin_ = smem;                   // 38x40  (1520)
    float* t1   = smem + 1520;            // 82x40  (3280) -> ends 4800
    float* z    = smem + 4800;            // 82x84  (6888) -> ends 11688
    float* t2   = smem;                   // 82x36  (2952), reuses sin_/t1 region

    int tid = threadIdx.x;                // 256
    if (tid < 12) { fuf[tid] = fu[11 - tid]; fdf[tid] = fd[11 - tid]; }  // pre-flip
    for (int e = tid; e < NPIX; e += 256) sin_[(e/38)*40 + (e%38)] = src[e];
    __syncthreads();

    // vertical zero-insert-upsample FIR: t1[u][c], u in [0,82)
    for (int e = tid; e < 82*38; e += 256) {
        int c = e % 38, u = e / 38;
        float a = 0.f;
        #pragma unroll
        for (int t = 0; t < 12; t++) {
            int m = u + t - 9;
            if (!(m & 1)) {
                int q = m >> 1;
                if (q >= 0 && q < 38) a += fuf[t]*sin_[q*40 + c];
            }
        }
        t1[u*40 + c] = a;
    }
    __syncthreads();

    // horizontal up FIR + gain(4) + lrelu*sqrt2 + clamp(256)
    for (int e = tid; e < 82*82; e += 256) {
        int v = e % 82, u = e / 82;
        float a = 0.f;
        #pragma unroll
        for (int t = 0; t < 12; t++) {
            int m = v + t - 9;
            if (!(m & 1)) {
                int q = m >> 1;
                if (q >= 0 && q < 38) a += fuf[t]*t1[u*40 + q];
            }
        }
        a *= 4.0f;
        a = (a >= 0.f ? a : 0.2f*a) * 1.4142135623730951f;
        a = fminf(fmaxf(a, -256.f), 256.f);
        z[u*84 + v] = a;
    }
    __syncthreads();

    // horizontal down FIR (decimate by 2)
    for (int e = tid; e < 82*36; e += 256) {
        int w = e % 36, u = e / 36;
        float a = 0.f;
        #pragma unroll
        for (int t = 0; t < 12; t++) a += fdf[t]*z[u*84 + 2*w + t];
        t2[u*36 + w] = a;
    }
    __syncthreads();

    // vertical down FIR + store
    for (int e = tid; e < NOUT; e += 256) {
        int w = e % 36, h = e / 36;
        float a = 0.f;
        #pragma unroll
        for (int t = 0; t < 12; t++) a += fdf[t]*t2[(2*h + t)*36 + w];
        dst[e] = a;
    }
}

// ---------------- launch ----------------
extern "C" void kernel_launch(void* const* d_in, const int* in_sizes, int n_in,
                              void* d_out, int out_size)
{
    const float* x    = (const float*)d_in[0];
    const float* w    = (const float*)d_in[1];
    const float* msg  = (const float*)d_in[2];
    const float* aw   = (const float*)d_in[3];
    const float* ab   = (const float*)d_in[4];
    const float* wt   = (const float*)d_in[5];
    const float* bias = (const float*)d_in[6];
    const float* ms   = (const float*)d_in[7];
    const float* mb   = (const float*)d_in[8];
    const float* fu   = (const float*)d_in[9];
    const float* fd   = (const float*)d_in[10];
    const float* ema  = (const float*)d_in[11];
    float* out = (float*)d_out;

    k_style   <<<16, 512>>>(w, msg, aw, ab, ms, mb, bias);
    k_wstats  <<<512, 256>>>(wt);
    k_outscale<<<dim3(4,16), 128>>>(ema);
    k_xpad    <<<(B_*CIN*HP*HP + 255)/256, 256>>>(x);
    k_conv    <<<dim3(12,4,16), 256>>>();
    k_fir     <<<B_*COUT, 256>>>(fu, fd, out);
}

// round 3
// speedup vs baseline: 2.3620x; 2.3620x over previous
#include <cuda_runtime.h>
#include <cuda_bf16.h>
#include <cstdint>

// ---------------- problem constants ----------------
#define B_    16
#define CIN   512
#define COUT  512
#define HS    36
#define NPIX  (38*38)      // valid conv output pixels
#define NOUT  (36*36)
#define QROWS 1792         // padded flat rows of gxT (1600 used + slack, zero tail)
#define BM    128
#define BN    128
#define BK    64
#define NCHUNK 72          // 9 taps * 8 cin-slices of 64
#define STAGE_BYTES 65536  // Ahi16K + Alo16K + Bhi16K + Blo16K

// ---------------- device scratch ----------------
__device__ float g_sn[B_*CIN];
__device__ float g_bmod[B_*COUT];
__device__ float g_r[COUT];
__device__ float g_S2t[CIN*COUT];
__device__ float g_outscale[B_*COUT];
__device__ __nv_bfloat16 g_xt_hi[(size_t)B_*QROWS*CIN];   // [b][q][i]; rows>=1600 stay zero
__device__ __nv_bfloat16 g_xt_lo[(size_t)B_*QROWS*CIN];
__device__ __nv_bfloat16 g_wa_hi[4*NCHUNK*BM*BK];         // [ot][chunk][o][j]
__device__ __nv_bfloat16 g_wa_lo[4*NCHUNK*BM*BK];
__device__ float g_conv[(size_t)B_*COUT*NPIX];

// ---------------- PTX helpers (baseline ISA only: sm_80-class) ----------------
__device__ __forceinline__ uint32_t smem_u32(const void* p) {
    uint32_t a;
    asm("{ .reg .u64 t; cvta.to.shared.u64 t, %1; cvt.u32.u64 %0, t; }" : "=r"(a) : "l"(p));
    return a;
}
__device__ __forceinline__ void cp_async16(uint32_t dst, const void* src) {
    asm volatile("cp.async.cg.shared.global [%0], [%1], 16;" :: "r"(dst), "l"(src) : "memory");
}
__device__ __forceinline__ void ldsm4(uint32_t* r, uint32_t addr) {
    asm volatile("ldmatrix.sync.aligned.m8n8.x4.shared.b16 {%0,%1,%2,%3}, [%4];"
        : "=r"(r[0]), "=r"(r[1]), "=r"(r[2]), "=r"(r[3]) : "r"(addr));
}
__device__ __forceinline__ void mma16816(float* c, const uint32_t* a, const uint32_t* b) {
    asm volatile("mma.sync.aligned.m16n8k16.row.col.f32.bf16.bf16.f32 "
        "{%0,%1,%2,%3}, {%4,%5,%6,%7}, {%8,%9}, {%0,%1,%2,%3};"
        : "+f"(c[0]), "+f"(c[1]), "+f"(c[2]), "+f"(c[3])
        : "r"(a[0]), "r"(a[1]), "r"(a[2]), "r"(a[3]), "r"(b[0]), "r"(b[1]));
}

// ================= K0: styles / bias =================
__global__ void k_style(const float* __restrict__ w, const float* __restrict__ msg,
                        const float* __restrict__ aw, const float* __restrict__ ab,
                        const float* __restrict__ ms, const float* __restrict__ mb,
                        const float* __restrict__ bias)
{
    int b = blockIdx.x, i = threadIdx.x;
    __shared__ float sw[512], sm[64], red[512];
    sw[i] = w[b*512 + i];
    if (i < 64) sm[i] = msg[b*64 + i];
    __syncthreads();
    float acc = ab[i];
    const float4* awr = (const float4*)(aw + (size_t)i*512);
    #pragma unroll 4
    for (int j4 = 0; j4 < 128; j4++) {
        float4 a = awr[j4];
        acc += sw[4*j4+0]*a.x + sw[4*j4+1]*a.y + sw[4*j4+2]*a.z + sw[4*j4+3]*a.w;
    }
    float macc = 0.f;
    #pragma unroll 8
    for (int m = 0; m < 64; m++) macc += sm[m]*ms[m*512 + i];
    acc += 0.01f*macc;
    red[i] = acc*acc;
    __syncthreads();
    for (int s = 256; s > 0; s >>= 1) { if (i < s) red[i] += red[i+s]; __syncthreads(); }
    g_sn[b*512+i] = acc * rsqrtf(red[0]*(1.0f/512.0f));
    float bacc = 0.f;
    #pragma unroll 8
    for (int m = 0; m < 64; m++) bacc += sm[m]*mb[m*512 + i];
    g_bmod[b*512+i] = bias[i] + 0.01f*bacc;
}

// ================= K1: weight stats =================
__global__ void k_wstats(const float* __restrict__ weight)
{
    int o = blockIdx.x, tid = threadIdx.x;
    __shared__ float red[256];
    float part = 0.f;
    for (int i = tid; i < 512; i += 256) {
        const float* wp = weight + ((size_t)o*512 + i)*9;
        float s2 = 0.f;
        #pragma unroll
        for (int k = 0; k < 9; k++) { float v = wp[k]; s2 += v*v; }
        g_S2t[i*512 + o] = s2;
        part += s2;
    }
    red[tid] = part;
    __syncthreads();
    for (int s = 128; s > 0; s >>= 1) { if (tid < s) red[tid] += red[tid+s]; __syncthreads(); }
    if (tid == 0) g_r[o] = rsqrtf(red[0]*(1.0f/4608.0f));
}

// ================= K2: demod scale =================
__global__ void k_outscale(const float* __restrict__ ema)
{
    int b = blockIdx.y;
    int o = blockIdx.x*128 + threadIdx.x;
    __shared__ float ssn2[512];
    for (int i = threadIdx.x; i < 512; i += 128) { float v = g_sn[b*512+i]; ssn2[i] = v*v; }
    __syncthreads();
    float acc = 0.f;
    #pragma unroll 4
    for (int i = 0; i < 512; i++) acc += ssn2[i]*g_S2t[i*512 + o];
    float r = g_r[o];
    g_outscale[b*512+o] = r * rsqrtf(r*r*acc + 1e-8f) * rsqrtf(ema[0]);
}

// ================= K3: x transpose + style-scale + bf16 split =================
// gxT[b][q][i] = bf16split( xpad(q) * sn[b][i] ), q flat over 40x40 padded grid
__global__ void k_xprep(const float* __restrict__ x)
{
    __shared__ float s[32][33];
    int tx = threadIdx.x, ty = threadIdx.y;
    int q0 = blockIdx.x*32, i0 = blockIdx.y*32, b = blockIdx.z;
    #pragma unroll
    for (int k = 0; k < 4; k++) {
        int ii = ty + k*8;
        int i = i0 + ii;
        int q = q0 + tx;
        int r = q/40, c = q%40;
        float v = 0.f;
        if (r >= 2 && r < 38 && c >= 2 && c < 38)
            v = x[((size_t)(b*512+i)*36 + (r-2))*36 + (c-2)];
        s[ii][tx] = v * g_sn[b*512+i];
    }
    __syncthreads();
    #pragma unroll
    for (int k = 0; k < 4; k++) {
        int qq = ty + k*8;
        int q = q0 + qq;
        float v = s[tx][qq];
        __nv_bfloat16 hi = __float2bfloat16(v);
        __nv_bfloat16 lo = __float2bfloat16(v - __bfloat162float(hi));
        size_t idx = ((size_t)b*QROWS + q)*512 + i0 + tx;
        g_xt_hi[idx] = hi;
        g_xt_lo[idx] = lo;
    }
}

// ================= K4: weight -> GEMM-A tiles + bf16 split =================
__global__ void k_wprep(const float* __restrict__ weight)
{
    int m = blockIdx.x, ot = blockIdx.y, tid = threadIdx.x;
    int tap = m >> 3, i0 = (m & 7)*64;
    for (int e = tid; e < 128*64; e += 256) {
        int ol = e >> 6, j = e & 63;
        float v = weight[(((size_t)(ot*128+ol))*512 + i0 + j)*9 + tap];
        __nv_bfloat16 hi = __float2bfloat16(v);
        __nv_bfloat16 lo = __float2bfloat16(v - __bfloat162float(hi));
        int idx = ((ot*NCHUNK + m)*128 + ol)*64 + j;
        g_wa_hi[idx] = hi;
        g_wa_lo[idx] = lo;
    }
}

// ================= K5: mma.sync bf16 implicit-GEMM conv =================
// CTA tile 128 Cout x 128 pixels; 8 warps (4M x 2N); warp tile 32x64.
// 3-pass split: Ah*Bh + Al*Bh + Ah*Bl. 2-stage cp.async pipeline.
struct KG {
    uint32_t sb;
    int b, ot, q0, tid;
    __device__ __forceinline__ void issue(int i, char* smem) {
        int p = i & 1;
        char* st = smem + p*STAGE_BYTES;
        uint32_t stu = sb + (uint32_t)p*STAGE_BYTES;
        int tap = i >> 3;
        int off = (tap/3)*40 + (tap%3);
        int i0c = (i & 7) * 64;
        const char* gah = (const char*)(g_wa_hi + ((size_t)(ot*NCHUNK + i))*BM*BK);
        const char* gal = (const char*)(g_wa_lo + ((size_t)(ot*NCHUNK + i))*BM*BK);
        const char* gbh = (const char*)(g_xt_hi + ((size_t)b*QROWS + q0 + off)*512 + i0c);
        const char* gbl = (const char*)(g_xt_lo + ((size_t)b*QROWS + q0 + off)*512 + i0c);
        (void)st;
        #pragma unroll
        for (int j = 0; j < 4; j++) {
            int e = tid + j*256;              // 0..1023
            int row = e >> 3, ch = e & 7;
            uint32_t sw = (uint32_t)row*128 + (uint32_t)((ch ^ (row & 7)) << 4);
            cp_async16(stu + sw,          gah + row*128 + ch*16);
            cp_async16(stu + 16384 + sw,  gal + row*128 + ch*16);
            cp_async16(stu + 32768 + sw,  gbh + (size_t)row*1024 + ch*16);
            cp_async16(stu + 49152 + sw,  gbl + (size_t)row*1024 + ch*16);
        }
        asm volatile("cp.async.commit_group;" ::: "memory");
    }
};

__global__ void __launch_bounds__(256) k_gemm()
{
    extern __shared__ char smem[];
    KG kg;
    kg.sb = smem_u32(smem);
    kg.b = blockIdx.z; kg.ot = blockIdx.y; kg.q0 = blockIdx.x * BN; kg.tid = threadIdx.x;
    const int lane = kg.tid & 31;
    const int wid = kg.tid >> 5;
    const int wm = wid & 3;          // 0..3  (M groups of 32)
    const int wn = wid >> 2;         // 0..1  (N groups of 64)

    float c[2][8][4];
    #pragma unroll
    for (int a = 0; a < 2; a++)
        #pragma unroll
        for (int bq = 0; bq < 8; bq++)
            #pragma unroll
            for (int k = 0; k < 4; k++) c[a][bq][k] = 0.f;

    kg.issue(0, smem);

    for (int i = 0; i < NCHUNK; i++) {
        if (i < NCHUNK-1) {
            kg.issue(i+1, smem);
            asm volatile("cp.async.wait_group 1;" ::: "memory");
        } else {
            asm volatile("cp.async.wait_group 0;" ::: "memory");
        }
        __syncthreads();

        uint32_t sbase = kg.sb + (uint32_t)(i & 1)*STAGE_BYTES;
        #pragma unroll
        for (int ks = 0; ks < 4; ks++) {
            uint32_t ah[2][4], al[2][4];
            #pragma unroll
            for (int mi = 0; mi < 2; mi++) {
                int row = wm*32 + mi*16 + (lane & 15);
                int ch  = ks*2 + (lane >> 4);
                uint32_t off = (uint32_t)row*128 + (uint32_t)((ch ^ (row & 7)) << 4);
                ldsm4(ah[mi], sbase + off);
                ldsm4(al[mi], sbase + 16384 + off);
            }
            uint32_t bh[4][4], bl[4][4];
            #pragma unroll
            for (int ni = 0; ni < 4; ni++) {
                int row = wn*64 + ni*16 + (lane & 7) + ((lane >> 4) << 3);
                int ch  = ks*2 + ((lane >> 3) & 1);
                uint32_t off = (uint32_t)row*128 + (uint32_t)((ch ^ (row & 7)) << 4);
                ldsm4(bh[ni], sbase + 32768 + off);
                ldsm4(bl[ni], sbase + 49152 + off);
            }
            #pragma unroll
            for (int mi = 0; mi < 2; mi++)
                #pragma unroll
                for (int ni = 0; ni < 4; ni++)
                    #pragma unroll
                    for (int half = 0; half < 2; half++) {
                        int nb = ni*2 + half;
                        mma16816(c[mi][nb], ah[mi], &bh[ni][half*2]);
                        mma16816(c[mi][nb], al[mi], &bh[ni][half*2]);
                        mma16816(c[mi][nb], ah[mi], &bl[ni][half*2]);
                    }
        }
        __syncthreads();
    }

    // epilogue: scale + bias, write valid pixels
    #pragma unroll
    for (int mi = 0; mi < 2; mi++) {
        int o0 = kg.ot*128 + wm*32 + mi*16 + (lane >> 2);
        float sc0 = g_outscale[kg.b*512 + o0],     bb0 = g_bmod[kg.b*512 + o0];
        float sc8 = g_outscale[kg.b*512 + o0 + 8], bb8 = g_bmod[kg.b*512 + o0 + 8];
        float* d0 = g_conv + ((size_t)(kg.b*512 + o0))*NPIX;
        float* d8 = g_conv + ((size_t)(kg.b*512 + o0 + 8))*NPIX;
        #pragma unroll
        for (int nb = 0; nb < 8; nb++) {
            int q = kg.q0 + wn*64 + nb*8 + 2*(lane & 3);
            int rr = q/40, cc = q - rr*40;
            if (rr < 38 && cc < 38) {
                int oi = rr*38 + cc;
                d0[oi]   = c[mi][nb][0]*sc0 + bb0;
                d0[oi+1] = c[mi][nb][1]*sc0 + bb0;
                d8[oi]   = c[mi][nb][2]*sc8 + bb8;
                d8[oi+1] = c[mi][nb][3]*sc8 + bb8;
            }
        }
    }
}

// ================= K6: fused filtered_lrelu (proven round-1 version) =================
__global__ void k_fir(const float* __restrict__ fu, const float* __restrict__ fd,
                      float* __restrict__ out)
{
    int plane = blockIdx.x;
    const float* src = g_conv + (size_t)plane*NPIX;
    float* dst = out + (size_t)plane*NOUT;

    __shared__ float smem[11688];
    __shared__ float fuf[12], fdf[12];
    float* sin_ = smem;                   // 38x40
    float* t1   = smem + 1520;            // 82x40
    float* z    = smem + 4800;            // 82x84
    float* t2   = smem;                   // 82x36 (reuse)

    int tid = threadIdx.x;
    if (tid < 12) { fuf[tid] = fu[11 - tid]; fdf[tid] = fd[11 - tid]; }
    for (int e = tid; e < NPIX; e += 256) sin_[(e/38)*40 + (e%38)] = src[e];
    __syncthreads();

    for (int e = tid; e < 82*38; e += 256) {
        int c = e % 38, u = e / 38;
        float a = 0.f;
        #pragma unroll
        for (int t = 0; t < 12; t++) {
            int m = u + t - 9;
            if (!(m & 1)) {
                int q = m >> 1;
                if (q >= 0 && q < 38) a += fuf[t]*sin_[q*40 + c];
            }
        }
        t1[u*40 + c] = a;
    }
    __syncthreads();

    for (int e = tid; e < 82*82; e += 256) {
        int v = e % 82, u = e / 82;
        float a = 0.f;
        #pragma unroll
        for (int t = 0; t < 12; t++) {
            int m = v + t - 9;
            if (!(m & 1)) {
                int q = m >> 1;
                if (q >= 0 && q < 38) a += fuf[t]*t1[u*40 + q];
            }
        }
        a *= 4.0f;
        a = (a >= 0.f ? a : 0.2f*a) * 1.4142135623730951f;
        a = fminf(fmaxf(a, -256.f), 256.f);
        z[u*84 + v] = a;
    }
    __syncthreads();

    for (int e = tid; e < 82*36; e += 256) {
        int w = e % 36, u = e / 36;
        float a = 0.f;
        #pragma unroll
        for (int t = 0; t < 12; t++) a += fdf[t]*z[u*84 + 2*w + t];
        t2[u*36 + w] = a;
    }
    __syncthreads();

    for (int e = tid; e < NOUT; e += 256) {
        int w = e % 36, h = e / 36;
        float a = 0.f;
        #pragma unroll
        for (int t = 0; t < 12; t++) a += fdf[t]*t2[(2*h + t)*36 + w];
        dst[e] = a;
    }
}

// ================= launch =================
extern "C" void kernel_launch(void* const* d_in, const int* in_sizes, int n_in,
                              void* d_out, int out_size)
{
    const float* x    = (const float*)d_in[0];
    const float* w    = (const float*)d_in[1];
    const float* msg  = (const float*)d_in[2];
    const float* aw   = (const float*)d_in[3];
    const float* ab   = (const float*)d_in[4];
    const float* wt   = (const float*)d_in[5];
    const float* bias = (const float*)d_in[6];
    const float* ms   = (const float*)d_in[7];
    const float* mb   = (const float*)d_in[8];
    const float* fu   = (const float*)d_in[9];
    const float* fd   = (const float*)d_in[10];
    const float* ema  = (const float*)d_in[11];
    float* out = (float*)d_out;

    static bool attr_set = false;
    if (!attr_set) {
        cudaFuncSetAttribute(k_gemm, cudaFuncAttributeMaxDynamicSharedMemorySize, 2*STAGE_BYTES);
        attr_set = true;
    }

    k_style   <<<16, 512>>>(w, msg, aw, ab, ms, mb, bias);
    k_wstats  <<<512, 256>>>(wt);
    k_outscale<<<dim3(4,16), 128>>>(ema);
    k_xprep   <<<dim3(50,16,16), dim3(32,8)>>>(x);
    k_wprep   <<<dim3(72,4), 256>>>(wt);
    k_gemm    <<<dim3(13,4,16), 256, 2*STAGE_BYTES>>>();
    k_fir     <<<B_*COUT, 256>>>(fu, fd, out);
}

// round 4
// speedup vs baseline: 3.0425x; 1.2881x over previous
#include <cuda_runtime.h>
#include <cuda_bf16.h>
#include <cstdint>

// ---------------- problem constants ----------------
#define B_    16
#define CIN   512
#define COUT  512
#define HS    36
#define NPIX  (38*38)      // valid conv output pixels
#define NOUT  (36*36)
#define QROWS 1792         // padded flat rows of gxT (1600 used + slack, zero tail)
#define BM    128
#define BN    128
#define BK    64
#define NCHUNK 72          // 9 taps * 8 cin-slices of 64
#define STAGE_BYTES 65536  // Ahi16K + Alo16K + Bhi16K + Blo16K
#define NSTAGE 3

// ---------------- device scratch ----------------
__device__ float g_sn[B_*CIN];
__device__ float g_bmod[B_*COUT];
__device__ float g_r[COUT];
__device__ float g_S2t[CIN*COUT];
__device__ float g_outscale[B_*COUT];
__device__ __nv_bfloat16 g_xt_hi[(size_t)B_*QROWS*CIN];   // [b][q][i]; rows>=1600 stay zero
__device__ __nv_bfloat16 g_xt_lo[(size_t)B_*QROWS*CIN];
__device__ __nv_bfloat16 g_wa_hi[4*NCHUNK*BM*BK];         // [ot][chunk][o][j]
__device__ __nv_bfloat16 g_wa_lo[4*NCHUNK*BM*BK];
__device__ float g_conv[(size_t)B_*COUT*NPIX];

// ---------------- PTX helpers (baseline ISA only) ----------------
__device__ __forceinline__ uint32_t smem_u32(const void* p) {
    uint32_t a;
    asm("{ .reg .u64 t; cvta.to.shared.u64 t, %1; cvt.u32.u64 %0, t; }" : "=r"(a) : "l"(p));
    return a;
}
__device__ __forceinline__ void cp_async16(uint32_t dst, const void* src) {
    asm volatile("cp.async.cg.shared.global [%0], [%1], 16;" :: "r"(dst), "l"(src) : "memory");
}
__device__ __forceinline__ void ldsm4(uint32_t* r, uint32_t addr) {
    asm volatile("ldmatrix.sync.aligned.m8n8.x4.shared.b16 {%0,%1,%2,%3}, [%4];"
        : "=r"(r[0]), "=r"(r[1]), "=r"(r[2]), "=r"(r[3]) : "r"(addr));
}
__device__ __forceinline__ void mma16816(float* c, const uint32_t* a, const uint32_t* b) {
    asm volatile("mma.sync.aligned.m16n8k16.row.col.f32.bf16.bf16.f32 "
        "{%0,%1,%2,%3}, {%4,%5,%6,%7}, {%8,%9}, {%0,%1,%2,%3};"
        : "+f"(c[0]), "+f"(c[1]), "+f"(c[2]), "+f"(c[3])
        : "r"(a[0]), "r"(a[1]), "r"(a[2]), "r"(a[3]), "r"(b[0]), "r"(b[1]));
}

// ================= K0: styles / bias =================
__global__ void k_style(const float* __restrict__ w, const float* __restrict__ msg,
                        const float* __restrict__ aw, const float* __restrict__ ab,
                        const float* __restrict__ ms, const float* __restrict__ mb,
                        const float* __restrict__ bias)
{
    int b = blockIdx.x, i = threadIdx.x;
    __shared__ float sw[512], sm[64], red[512];
    sw[i] = w[b*512 + i];
    if (i < 64) sm[i] = msg[b*64 + i];
    __syncthreads();
    float acc = ab[i];
    const float4* awr = (const float4*)(aw + (size_t)i*512);
    #pragma unroll 4
    for (int j4 = 0; j4 < 128; j4++) {
        float4 a = awr[j4];
        acc += sw[4*j4+0]*a.x + sw[4*j4+1]*a.y + sw[4*j4+2]*a.z + sw[4*j4+3]*a.w;
    }
    float macc = 0.f;
    #pragma unroll 8
    for (int m = 0; m < 64; m++) macc += sm[m]*ms[m*512 + i];
    acc += 0.01f*macc;
    red[i] = acc*acc;
    __syncthreads();
    for (int s = 256; s > 0; s >>= 1) { if (i < s) red[i] += red[i+s]; __syncthreads(); }
    g_sn[b*512+i] = acc * rsqrtf(red[0]*(1.0f/512.0f));
    float bacc = 0.f;
    #pragma unroll 8
    for (int m = 0; m < 64; m++) bacc += sm[m]*mb[m*512 + i];
    g_bmod[b*512+i] = bias[i] + 0.01f*bacc;
}

// ================= K1: weight stats =================
__global__ void k_wstats(const float* __restrict__ weight)
{
    int o = blockIdx.x, tid = threadIdx.x;
    __shared__ float red[256];
    float part = 0.f;
    for (int i = tid; i < 512; i += 256) {
        const float* wp = weight + ((size_t)o*512 + i)*9;
        float s2 = 0.f;
        #pragma unroll
        for (int k = 0; k < 9; k++) { float v = wp[k]; s2 += v*v; }
        g_S2t[i*512 + o] = s2;
        part += s2;
    }
    red[tid] = part;
    __syncthreads();
    for (int s = 128; s > 0; s >>= 1) { if (tid < s) red[tid] += red[tid+s]; __syncthreads(); }
    if (tid == 0) g_r[o] = rsqrtf(red[0]*(1.0f/4608.0f));
}

// ================= K2: demod scale =================
__global__ void k_outscale(const float* __restrict__ ema)
{
    int b = blockIdx.y;
    int o = blockIdx.x*128 + threadIdx.x;
    __shared__ float ssn2[512];
    for (int i = threadIdx.x; i < 512; i += 128) { float v = g_sn[b*512+i]; ssn2[i] = v*v; }
    __syncthreads();
    float acc = 0.f;
    #pragma unroll 4
    for (int i = 0; i < 512; i++) acc += ssn2[i]*g_S2t[i*512 + o];
    float r = g_r[o];
    g_outscale[b*512+o] = r * rsqrtf(r*r*acc + 1e-8f) * rsqrtf(ema[0]);
}

// ================= K3: x transpose + style-scale + bf16 split =================
__global__ void k_xprep(const float* __restrict__ x)
{
    __shared__ float s[32][33];
    int tx = threadIdx.x, ty = threadIdx.y;
    int q0 = blockIdx.x*32, i0 = blockIdx.y*32, b = blockIdx.z;
    #pragma unroll
    for (int k = 0; k < 4; k++) {
        int ii = ty + k*8;
        int i = i0 + ii;
        int q = q0 + tx;
        int r = q/40, c = q%40;
        float v = 0.f;
        if (r >= 2 && r < 38 && c >= 2 && c < 38)
            v = x[((size_t)(b*512+i)*36 + (r-2))*36 + (c-2)];
        s[ii][tx] = v * g_sn[b*512+i];
    }
    __syncthreads();
    #pragma unroll
    for (int k = 0; k < 4; k++) {
        int qq = ty + k*8;
        int q = q0 + qq;
        float v = s[tx][qq];
        __nv_bfloat16 hi = __float2bfloat16(v);
        __nv_bfloat16 lo = __float2bfloat16(v - __bfloat162float(hi));
        size_t idx = ((size_t)b*QROWS + q)*512 + i0 + tx;
        g_xt_hi[idx] = hi;
        g_xt_lo[idx] = lo;
    }
}

// ================= K4: weight -> GEMM-A tiles + bf16 split =================
__global__ void k_wprep(const float* __restrict__ weight)
{
    int m = blockIdx.x, ot = blockIdx.y, tid = threadIdx.x;
    int tap = m >> 3, i0 = (m & 7)*64;
    for (int e = tid; e < 128*64; e += 256) {
        int ol = e >> 6, j = e & 63;
        float v = weight[(((size_t)(ot*128+ol))*512 + i0 + j)*9 + tap];
        __nv_bfloat16 hi = __float2bfloat16(v);
        __nv_bfloat16 lo = __float2bfloat16(v - __bfloat162float(hi));
        int idx = ((ot*NCHUNK + m)*128 + ol)*64 + j;
        g_wa_hi[idx] = hi;
        g_wa_lo[idx] = lo;
    }
}

// ================= K5: mma.sync bf16 implicit-GEMM conv (3-stage) =================
struct KG {
    uint32_t sb;
    int b, ot, q0, tid;
    __device__ __forceinline__ void issue(int i, int stage) {
        uint32_t stu = sb + (uint32_t)stage*STAGE_BYTES;
        int tap = i >> 3;
        int off = (tap/3)*40 + (tap%3);
        int i0c = (i & 7) * 64;
        const char* gah = (const char*)(g_wa_hi + ((size_t)(ot*NCHUNK + i))*BM*BK);
        const char* gal = (const char*)(g_wa_lo + ((size_t)(ot*NCHUNK + i))*BM*BK);
        const char* gbh = (const char*)(g_xt_hi + ((size_t)b*QROWS + q0 + off)*512 + i0c);
        const char* gbl = (const char*)(g_xt_lo + ((size_t)b*QROWS + q0 + off)*512 + i0c);
        #pragma unroll
        for (int j = 0; j < 4; j++) {
            int e = tid + j*256;              // 0..1023
            int row = e >> 3, ch = e & 7;
            uint32_t sw = (uint32_t)row*128 + (uint32_t)((ch ^ (row & 7)) << 4);
            cp_async16(stu + sw,          gah + row*128 + ch*16);
            cp_async16(stu + 16384 + sw,  gal + row*128 + ch*16);
            cp_async16(stu + 32768 + sw,  gbh + (size_t)row*1024 + ch*16);
            cp_async16(stu + 49152 + sw,  gbl + (size_t)row*1024 + ch*16);
        }
        asm volatile("cp.async.commit_group;" ::: "memory");
    }
};

__global__ void __launch_bounds__(256) k_gemm()
{
    extern __shared__ char smem[];
    KG kg;
    kg.sb = smem_u32(smem);
    kg.b = blockIdx.z; kg.ot = blockIdx.y; kg.q0 = blockIdx.x * BN; kg.tid = threadIdx.x;
    const int lane = kg.tid & 31;
    const int wid = kg.tid >> 5;
    const int wm = wid & 3;          // 0..3  (M groups of 32)
    const int wn = wid >> 2;         // 0..1  (N groups of 64)

    float c[2][8][4];
    #pragma unroll
    for (int a = 0; a < 2; a++)
        #pragma unroll
        for (int bq = 0; bq < 8; bq++)
            #pragma unroll
            for (int k = 0; k < 4; k++) c[a][bq][k] = 0.f;

    kg.issue(0, 0);
    kg.issue(1, 1);

    int cstage = 0;                   // i % 3
    for (int i = 0; i < NCHUNK; i++) {
        if (i < NCHUNK-1) asm volatile("cp.async.wait_group 1;" ::: "memory");
        else              asm volatile("cp.async.wait_group 0;" ::: "memory");
        __syncthreads();

        if (i + 2 < NCHUNK) {
            int ns = cstage + 2; if (ns >= NSTAGE) ns -= NSTAGE;
            kg.issue(i + 2, ns);
        }

        uint32_t sbase = kg.sb + (uint32_t)cstage*STAGE_BYTES;
        #pragma unroll
        for (int ks = 0; ks < 4; ks++) {
            uint32_t ah[2][4], al[2][4];
            #pragma unroll
            for (int mi = 0; mi < 2; mi++) {
                int row = wm*32 + mi*16 + (lane & 15);
                int ch  = ks*2 + (lane >> 4);
                uint32_t off = (uint32_t)row*128 + (uint32_t)((ch ^ (row & 7)) << 4);
                ldsm4(ah[mi], sbase + off);
                ldsm4(al[mi], sbase + 16384 + off);
            }
            uint32_t bh[4][4], bl[4][4];
            #pragma unroll
            for (int ni = 0; ni < 4; ni++) {
                int row = wn*64 + ni*16 + (lane & 7) + ((lane >> 4) << 3);
                int ch  = ks*2 + ((lane >> 3) & 1);
                uint32_t off = (uint32_t)row*128 + (uint32_t)((ch ^ (row & 7)) << 4);
                ldsm4(bh[ni], sbase + 32768 + off);
                ldsm4(bl[ni], sbase + 49152 + off);
            }
            #pragma unroll
            for (int mi = 0; mi < 2; mi++)
                #pragma unroll
                for (int ni = 0; ni < 4; ni++)
                    #pragma unroll
                    for (int half = 0; half < 2; half++) {
                        int nb = ni*2 + half;
                        mma16816(c[mi][nb], ah[mi], &bh[ni][half*2]);
                        mma16816(c[mi][nb], al[mi], &bh[ni][half*2]);
                        mma16816(c[mi][nb], ah[mi], &bl[ni][half*2]);
                    }
        }
        cstage++; if (cstage >= NSTAGE) cstage = 0;
    }

    // epilogue: scale + bias, write valid pixels
    #pragma unroll
    for (int mi = 0; mi < 2; mi++) {
        int o0 = kg.ot*128 + wm*32 + mi*16 + (lane >> 2);
        float sc0 = g_outscale[kg.b*512 + o0],     bb0 = g_bmod[kg.b*512 + o0];
        float sc8 = g_outscale[kg.b*512 + o0 + 8], bb8 = g_bmod[kg.b*512 + o0 + 8];
        float* d0 = g_conv + ((size_t)(kg.b*512 + o0))*NPIX;
        float* d8 = g_conv + ((size_t)(kg.b*512 + o0 + 8))*NPIX;
        #pragma unroll
        for (int nb = 0; nb < 8; nb++) {
            int q = kg.q0 + wn*64 + nb*8 + 2*(lane & 3);
            int rr = q/40, cc = q - rr*40;
            if (rr < 38 && cc < 38) {
                int oi = rr*38 + cc;
                d0[oi]   = c[mi][nb][0]*sc0 + bb0;
                d0[oi+1] = c[mi][nb][1]*sc0 + bb0;
                d8[oi]   = c[mi][nb][2]*sc8 + bb8;
                d8[oi+1] = c[mi][nb][3]*sc8 + bb8;
            }
        }
    }
}

// ================= K6: fused filtered_lrelu (branchless, parity-hoisted) =================
// SMEM liveness-aliased layout (floats):
//   t1p  : [0, 3936)        82 rows x 48 cols (padded up-FIR intermediate)
//   sin_p: [3936, 5776)     46 rows x 40 cols (4-row zero pad each side); dead after P1
//   z    : [3936, 10824)    82 x 84; overlays sin_p (written in P2 after sin_p dead)
//   t2   : [0, 2952)        82 x 36; overlays t1p (written in P3 after t1p dead)
__global__ void k_fir(const float* __restrict__ fu, const float* __restrict__ fd,
                      float* __restrict__ out)
{
    int plane = blockIdx.x;
    const float* src = g_conv + (size_t)plane*NPIX;
    float* dst = out + (size_t)plane*NOUT;

    __shared__ float smem[10824];
    __shared__ float fuf[12], fdf[12];
    float* t1p  = smem;            // stride 48, cols: pad4 | 38 data | pad4 | 2 unused
    float* sinp = smem + 3936;     // stride 40, rows: pad4 | 38 data | pad4
    float* z    = smem + 3936;     // stride 84
    float* t2   = smem;            // stride 36

    int tid = threadIdx.x;         // 256
    if (tid < 12) { fuf[tid] = fu[11 - tid]; fdf[tid] = fd[11 - tid]; }
    // fill sin_p (zero pad rows)
    for (int e = tid; e < 46*40; e += 256) {
        int c = e % 40, r = e / 40;
        float v = 0.f;
        int rr = r - 4;
        if (rr >= 0 && rr < 38 && c < 38) v = src[rr*38 + c];
        sinp[e] = v;
    }
    __syncthreads();

    // P1: vertical up-FIR -> t1p  (pad cols written as zero)
    for (int e = tid; e < 82*46; e += 256) {
        int qc = e % 46, u = e / 46;
        int c = qc - 4;
        int t0 = (u & 1) ^ 1;
        int base = ((u + t0 - 9) >> 1) + 4;     // sin_p row index, in [0,40]
        float a = 0.f;
        if (c >= 0 && c < 38) {
            const float* sp = sinp + base*40 + c;
            #pragma unroll
            for (int s = 0; s < 6; s++) a += fuf[t0 + 2*s]*sp[s*40];
        }
        t1p[u*48 + qc] = a;
    }
    __syncthreads();

    // P2: horizontal up-FIR + gain + lrelu + clamp -> z
    for (int e = tid; e < 82*82; e += 256) {
        int v = e % 82, u = e / 82;
        int t0 = (v & 1) ^ 1;
        int base = ((v + t0 - 9) >> 1) + 4;     // t1p col index, in [0,40]
        const float* tp = t1p + u*48 + base;
        float a = 0.f;
        #pragma unroll
        for (int s = 0; s < 6; s++) a += fuf[t0 + 2*s]*tp[s];
        a *= 4.0f;
        a = (a >= 0.f ? a : 0.2f*a) * 1.4142135623730951f;
        a = fminf(fmaxf(a, -256.f), 256.f);
        z[u*84 + v] = a;
    }
    __syncthreads();

    // P3: horizontal down-FIR -> t2
    for (int e = tid; e < 82*36; e += 256) {
        int w = e % 36, u = e / 36;
        const float* zp = z + u*84 + 2*w;
        float a = 0.f;
        #pragma unroll
        for (int t = 0; t < 12; t++) a += fdf[t]*zp[t];
        t2[u*36 + w] = a;
    }
    __syncthreads();

    // P4: vertical down-FIR -> out
    for (int e = tid; e < NOUT; e += 256) {
        int w = e % 36, h = e / 36;
        const float* tp = t2 + 2*h*36 + w;
        float a = 0.f;
        #pragma unroll
        for (int t = 0; t < 12; t++) a += fdf[t]*tp[t*36];
        dst[e] = a;
    }
}

// ================= launch =================
extern "C" void kernel_launch(void* const* d_in, const int* in_sizes, int n_in,
                              void* d_out, int out_size)
{
    const float* x    = (const float*)d_in[0];
    const float* w    = (const float*)d_in[1];
    const float* msg  = (const float*)d_in[2];
    const float* aw   = (const float*)d_in[3];
    const float* ab   = (const float*)d_in[4];
    const float* wt   = (const float*)d_in[5];
    const float* bias = (const float*)d_in[6];
    const float* ms   = (const float*)d_in[7];
    const float* mb   = (const float*)d_in[8];
    const float* fu   = (const float*)d_in[9];
    const float* fd   = (const float*)d_in[10];
    const float* ema  = (const float*)d_in[11];
    float* out = (float*)d_out;

    static bool attr_set = false;
    if (!attr_set) {
        cudaFuncSetAttribute(k_gemm, cudaFuncAttributeMaxDynamicSharedMemorySize, NSTAGE*STAGE_BYTES);
        attr_set = true;
    }

    k_style   <<<16, 512>>>(w, msg, aw, ab, ms, mb, bias);
    k_wstats  <<<512, 256>>>(wt);
    k_outscale<<<dim3(4,16), 128>>>(ema);
    k_xprep   <<<dim3(50,16,16), dim3(32,8)>>>(x);
    k_wprep   <<<dim3(72,4), 256>>>(wt);
    k_gemm    <<<dim3(13,4,16), 256, NSTAGE*STAGE_BYTES>>>();
    k_fir     <<<B_*COUT, 256>>>(fu, fd, out);
}

// round 5
// speedup vs baseline: 5.8819x; 1.9332x over previous
#include <cuda_runtime.h>
#include <cuda_fp16.h>
#include <cstdint>

// ---------------- problem constants ----------------
#define B_    16
#define CIN   512
#define COUT  512
#define HS    36
#define NPIX  (38*38)      // valid conv output pixels
#define NOUT  (36*36)
#define QROWS 1792         // padded flat rows of gxT (1600 used + zero tail)
#define BM    128
#define BN    128
#define BK    64
#define NCHUNK 72          // 9 taps * 8 cin-slices of 64
#define STAGE_BYTES 32768  // A 16K + B 16K (fp16)
#define NSTAGE 3

// ---------------- device scratch ----------------
__device__ float g_sn[B_*CIN];
__device__ float g_bmod[B_*COUT];
__device__ float g_r[COUT];
__device__ float g_S2t[CIN*COUT];
__device__ float g_outscale[B_*COUT];
__device__ __half g_xt[(size_t)B_*QROWS*CIN];     // [b][q][i]; rows>=1600 stay zero
__device__ __half g_wa[4*NCHUNK*BM*BK];           // [ot][chunk][o][j]
__device__ float g_conv[(size_t)B_*COUT*NPIX];

// ---------------- PTX helpers (baseline ISA only) ----------------
__device__ __forceinline__ uint32_t smem_u32(const void* p) {
    uint32_t a;
    asm("{ .reg .u64 t; cvta.to.shared.u64 t, %1; cvt.u32.u64 %0, t; }" : "=r"(a) : "l"(p));
    return a;
}
__device__ __forceinline__ void cp_async16(uint32_t dst, const void* src) {
    asm volatile("cp.async.cg.shared.global [%0], [%1], 16;" :: "r"(dst), "l"(src) : "memory");
}
__device__ __forceinline__ void ldsm4(uint32_t* r, uint32_t addr) {
    asm volatile("ldmatrix.sync.aligned.m8n8.x4.shared.b16 {%0,%1,%2,%3}, [%4];"
        : "=r"(r[0]), "=r"(r[1]), "=r"(r[2]), "=r"(r[3]) : "r"(addr));
}
__device__ __forceinline__ void mma16816(float* c, const uint32_t* a, const uint32_t* b) {
    asm volatile("mma.sync.aligned.m16n8k16.row.col.f32.f16.f16.f32 "
        "{%0,%1,%2,%3}, {%4,%5,%6,%7}, {%8,%9}, {%0,%1,%2,%3};"
        : "+f"(c[0]), "+f"(c[1]), "+f"(c[2]), "+f"(c[3])
        : "r"(a[0]), "r"(a[1]), "r"(a[2]), "r"(a[3]), "r"(b[0]), "r"(b[1]));
}

// ================= K0: styles / bias =================
__global__ void k_style(const float* __restrict__ w, const float* __restrict__ msg,
                        const float* __restrict__ aw, const float* __restrict__ ab,
                        const float* __restrict__ ms, const float* __restrict__ mb,
                        const float* __restrict__ bias)
{
    int b = blockIdx.x, i = threadIdx.x;
    __shared__ float sw[512], sm[64], red[512];
    sw[i] = w[b*512 + i];
    if (i < 64) sm[i] = msg[b*64 + i];
    __syncthreads();
    float acc = ab[i];
    const float4* awr = (const float4*)(aw + (size_t)i*512);
    #pragma unroll 4
    for (int j4 = 0; j4 < 128; j4++) {
        float4 a = awr[j4];
        acc += sw[4*j4+0]*a.x + sw[4*j4+1]*a.y + sw[4*j4+2]*a.z + sw[4*j4+3]*a.w;
    }
    float macc = 0.f;
    #pragma unroll 8
    for (int m = 0; m < 64; m++) macc += sm[m]*ms[m*512 + i];
    acc += 0.01f*macc;
    red[i] = acc*acc;
    __syncthreads();
    for (int s = 256; s > 0; s >>= 1) { if (i < s) red[i] += red[i+s]; __syncthreads(); }
    g_sn[b*512+i] = acc * rsqrtf(red[0]*(1.0f/512.0f));
    float bacc = 0.f;
    #pragma unroll 8
    for (int m = 0; m < 64; m++) bacc += sm[m]*mb[m*512 + i];
    g_bmod[b*512+i] = bias[i] + 0.01f*bacc;
}

// ================= K1: weight stats =================
__global__ void k_wstats(const float* __restrict__ weight)
{
    int o = blockIdx.x, tid = threadIdx.x;
    __shared__ float red[256];
    float part = 0.f;
    for (int i = tid; i < 512; i += 256) {
        const float* wp = weight + ((size_t)o*512 + i)*9;
        float s2 = 0.f;
        #pragma unroll
        for (int k = 0; k < 9; k++) { float v = wp[k]; s2 += v*v; }
        g_S2t[i*512 + o] = s2;
        part += s2;
    }
    red[tid] = part;
    __syncthreads();
    for (int s = 128; s > 0; s >>= 1) { if (tid < s) red[tid] += red[tid+s]; __syncthreads(); }
    if (tid == 0) g_r[o] = rsqrtf(red[0]*(1.0f/4608.0f));
}

// ================= K2: demod scale =================
__global__ void k_outscale(const float* __restrict__ ema)
{
    int b = blockIdx.y;
    int o = blockIdx.x*128 + threadIdx.x;
    __shared__ float ssn2[512];
    for (int i = threadIdx.x; i < 512; i += 128) { float v = g_sn[b*512+i]; ssn2[i] = v*v; }
    __syncthreads();
    float acc = 0.f;
    #pragma unroll 4
    for (int i = 0; i < 512; i++) acc += ssn2[i]*g_S2t[i*512 + o];
    float r = g_r[o];
    g_outscale[b*512+o] = r * rsqrtf(r*r*acc + 1e-8f) * rsqrtf(ema[0]);
}

// ================= K3: x transpose + style-scale + fp16 =================
__global__ void k_xprep(const float* __restrict__ x)
{
    __shared__ float s[32][33];
    int tx = threadIdx.x, ty = threadIdx.y;
    int q0 = blockIdx.x*32, i0 = blockIdx.y*32, b = blockIdx.z;
    #pragma unroll
    for (int k = 0; k < 4; k++) {
        int ii = ty + k*8;
        int i = i0 + ii;
        int q = q0 + tx;
        int r = q/40, c = q%40;
        float v = 0.f;
        if (r >= 2 && r < 38 && c >= 2 && c < 38)
            v = x[((size_t)(b*512+i)*36 + (r-2))*36 + (c-2)];
        s[ii][tx] = v * g_sn[b*512+i];
    }
    __syncthreads();
    #pragma unroll
    for (int k = 0; k < 4; k++) {
        int qq = ty + k*8;
        int q = q0 + qq;
        g_xt[((size_t)b*QROWS + q)*512 + i0 + tx] = __float2half(s[tx][qq]);
    }
}

// ================= K4: weight -> GEMM-A tiles (fp16) =================
__global__ void k_wprep(const float* __restrict__ weight)
{
    int m = blockIdx.x, ot = blockIdx.y, tid = threadIdx.x;
    int tap = m >> 3, i0 = (m & 7)*64;
    for (int e = tid; e < 128*64; e += 256) {
        int ol = e >> 6, j = e & 63;
        float v = weight[(((size_t)(ot*128+ol))*512 + i0 + j)*9 + tap];
        g_wa[((ot*NCHUNK + m)*128 + ol)*64 + j] = __float2half(v);
    }
}

// ================= K5: mma.sync fp16 implicit-GEMM conv (3-stage, 2 CTA/SM) ==========
struct KG {
    uint32_t sb;
    int b, ot, q0, tid;
    __device__ __forceinline__ void issue(int i, int stage) {
        uint32_t stu = sb + (uint32_t)stage*STAGE_BYTES;
        int tap = i >> 3;
        int off = (tap/3)*40 + (tap%3);
        int i0c = (i & 7) * 64;
        const char* ga = (const char*)(g_wa + ((size_t)(ot*NCHUNK + i))*BM*BK);
        const char* gb = (const char*)(g_xt + ((size_t)b*QROWS + q0 + off)*512 + i0c);
        #pragma unroll
        for (int j = 0; j < 4; j++) {
            int e = tid + j*256;              // 0..1023
            int row = e >> 3, ch = e & 7;
            uint32_t sw = (uint32_t)row*128 + (uint32_t)((ch ^ (row & 7)) << 4);
            cp_async16(stu + sw,          ga + row*128 + ch*16);
            cp_async16(stu + 16384 + sw,  gb + (size_t)row*1024 + ch*16);
        }
        asm volatile("cp.async.commit_group;" ::: "memory");
    }
};

__global__ void __launch_bounds__(256, 2) k_gemm()
{
    extern __shared__ char smem[];
    KG kg;
    kg.sb = smem_u32(smem);
    kg.b = blockIdx.z; kg.ot = blockIdx.y; kg.q0 = blockIdx.x * BN; kg.tid = threadIdx.x;
    const int lane = kg.tid & 31;
    const int wid = kg.tid >> 5;
    const int wm = wid & 3;          // 0..3  (M groups of 32)
    const int wn = wid >> 2;         // 0..1  (N groups of 64)

    float c[2][8][4];
    #pragma unroll
    for (int a = 0; a < 2; a++)
        #pragma unroll
        for (int bq = 0; bq < 8; bq++)
            #pragma unroll
            for (int k = 0; k < 4; k++) c[a][bq][k] = 0.f;

    kg.issue(0, 0);
    kg.issue(1, 1);

    int cstage = 0;
    for (int i = 0; i < NCHUNK; i++) {
        if (i < NCHUNK-1) asm volatile("cp.async.wait_group 1;" ::: "memory");
        else              asm volatile("cp.async.wait_group 0;" ::: "memory");
        __syncthreads();

        if (i + 2 < NCHUNK) {
            int ns = cstage + 2; if (ns >= NSTAGE) ns -= NSTAGE;
            kg.issue(i + 2, ns);
        }

        uint32_t sbase = kg.sb + (uint32_t)cstage*STAGE_BYTES;
        #pragma unroll
        for (int ks = 0; ks < 4; ks++) {
            uint32_t ah[2][4];
            #pragma unroll
            for (int mi = 0; mi < 2; mi++) {
                int row = wm*32 + mi*16 + (lane & 15);
                int ch  = ks*2 + (lane >> 4);
                uint32_t off = (uint32_t)row*128 + (uint32_t)((ch ^ (row & 7)) << 4);
                ldsm4(ah[mi], sbase + off);
            }
            uint32_t bh[4][4];
            #pragma unroll
            for (int ni = 0; ni < 4; ni++) {
                int row = wn*64 + ni*16 + (lane & 7) + ((lane >> 4) << 3);
                int ch  = ks*2 + ((lane >> 3) & 1);
                uint32_t off = (uint32_t)row*128 + (uint32_t)((ch ^ (row & 7)) << 4);
                ldsm4(bh[ni], sbase + 16384 + off);
            }
            #pragma unroll
            for (int mi = 0; mi < 2; mi++)
                #pragma unroll
                for (int ni = 0; ni < 4; ni++)
                    #pragma unroll
                    for (int half = 0; half < 2; half++)
                        mma16816(c[mi][ni*2+half], ah[mi], &bh[ni][half*2]);
        }
        cstage++; if (cstage >= NSTAGE) cstage = 0;
    }

    // epilogue: scale + bias, write valid pixels
    #pragma unroll
    for (int mi = 0; mi < 2; mi++) {
        int o0 = kg.ot*128 + wm*32 + mi*16 + (lane >> 2);
        float sc0 = g_outscale[kg.b*512 + o0],     bb0 = g_bmod[kg.b*512 + o0];
        float sc8 = g_outscale[kg.b*512 + o0 + 8], bb8 = g_bmod[kg.b*512 + o0 + 8];
        float* d0 = g_conv + ((size_t)(kg.b*512 + o0))*NPIX;
        float* d8 = g_conv + ((size_t)(kg.b*512 + o0 + 8))*NPIX;
        #pragma unroll
        for (int nb = 0; nb < 8; nb++) {
            int q = kg.q0 + wn*64 + nb*8 + 2*(lane & 3);
            int rr = q/40, cc = q - rr*40;
            if (rr < 38 && cc < 38) {
                int oi = rr*38 + cc;
                d0[oi]   = c[mi][nb][0]*sc0 + bb0;
                d0[oi+1] = c[mi][nb][1]*sc0 + bb0;
                d8[oi]   = c[mi][nb][2]*sc8 + bb8;
                d8[oi+1] = c[mi][nb][3]*sc8 + bb8;
            }
        }
    }
}

// ================= K6: fused filtered_lrelu (branchless, parity-hoisted) =================
__global__ void k_fir(const float* __restrict__ fu, const float* __restrict__ fd,
                      float* __restrict__ out)
{
    int plane = blockIdx.x;
    const float* src = g_conv + (size_t)plane*NPIX;
    float* dst = out + (size_t)plane*NOUT;

    __shared__ float smem[10824];
    __shared__ float fuf[12], fdf[12];
    float* t1p  = smem;            // stride 48
    float* sinp = smem + 3936;     // stride 40
    float* z    = smem + 3936;     // stride 84 (overlays sinp after P1)
    float* t2   = smem;            // stride 36 (overlays t1p after P2)

    int tid = threadIdx.x;         // 256
    if (tid < 12) { fuf[tid] = fu[11 - tid]; fdf[tid] = fd[11 - tid]; }
    for (int e = tid; e < 46*40; e += 256) {
        int c = e % 40, r = e / 40;
        float v = 0.f;
        int rr = r - 4;
        if (rr >= 0 && rr < 38 && c < 38) v = src[rr*38 + c];
        sinp[e] = v;
    }
    __syncthreads();

    for (int e = tid; e < 82*46; e += 256) {
        int qc = e % 46, u = e / 46;
        int c = qc - 4;
        int t0 = (u & 1) ^ 1;
        int base = ((u + t0 - 9) >> 1) + 4;
        float a = 0.f;
        if (c >= 0 && c < 38) {
            const float* sp = sinp + base*40 + c;
            #pragma unroll
            for (int s = 0; s < 6; s++) a += fuf[t0 + 2*s]*sp[s*40];
        }
        t1p[u*48 + qc] = a;
    }
    __syncthreads();

    for (int e = tid; e < 82*82; e += 256) {
        int v = e % 82, u = e / 82;
        int t0 = (v & 1) ^ 1;
        int base = ((v + t0 - 9) >> 1) + 4;
        const float* tp = t1p + u*48 + base;
        float a = 0.f;
        #pragma unroll
        for (int s = 0; s < 6; s++) a += fuf[t0 + 2*s]*tp[s];
        a *= 4.0f;
        a = (a >= 0.f ? a : 0.2f*a) * 1.4142135623730951f;
        a = fminf(fmaxf(a, -256.f), 256.f);
        z[u*84 + v] = a;
    }
    __syncthreads();

    for (int e = tid; e < 82*36; e += 256) {
        int w = e % 36, u = e / 36;
        const float* zp = z + u*84 + 2*w;
        float a = 0.f;
        #pragma unroll
        for (int t = 0; t < 12; t++) a += fdf[t]*zp[t];
        t2[u*36 + w] = a;
    }
    __syncthreads();

    for (int e = tid; e < NOUT; e += 256) {
        int w = e % 36, h = e / 36;
        const float* tp = t2 + 2*h*36 + w;
        float a = 0.f;
        #pragma unroll
        for (int t = 0; t < 12; t++) a += fdf[t]*tp[t*36];
        dst[e] = a;
    }
}

// ================= launch =================
extern "C" void kernel_launch(void* const* d_in, const int* in_sizes, int n_in,
                              void* d_out, int out_size)
{
    const float* x    = (const float*)d_in[0];
    const float* w    = (const float*)d_in[1];
    const float* msg  = (const float*)d_in[2];
    const float* aw   = (const float*)d_in[3];
    const float* ab   = (const float*)d_in[4];
    const float* wt   = (const float*)d_in[5];
    const float* bias = (const float*)d_in[6];
    const float* ms   = (const float*)d_in[7];
    const float* mb   = (const float*)d_in[8];
    const float* fu   = (const float*)d_in[9];
    const float* fd   = (const float*)d_in[10];
    const float* ema  = (const float*)d_in[11];
    float* out = (float*)d_out;

    static bool attr_set = false;
    if (!attr_set) {
        cudaFuncSetAttribute(k_gemm, cudaFuncAttributeMaxDynamicSharedMemorySize, NSTAGE*STAGE_BYTES);
        attr_set = true;
    }

    k_style   <<<16, 512>>>(w, msg, aw, ab, ms, mb, bias);
    k_wstats  <<<512, 256>>>(wt);
    k_outscale<<<dim3(4,16), 128>>>(ema);
    k_xprep   <<<dim3(50,16,16), dim3(32,8)>>>(x);
    k_wprep   <<<dim3(72,4), 256>>>(wt);
    k_gemm    <<<dim3(13,4,16), 256, NSTAGE*STAGE_BYTES>>>();
    k_fir     <<<B_*COUT, 256>>>(fu, fd, out);
}

// round 6
// speedup vs baseline: 6.7638x; 1.1499x over previous
#include <cuda_runtime.h>
#include <cuda_fp16.h>
#include <cstdint>

// ---------------- problem constants ----------------
#define B_    16
#define CIN   512
#define COUT  512
#define HS    36
#define NPIX  (38*38)
#define NOUT  (36*36)
#define QROWS 1792         // gxt rows; 0..1599 written, tail stays zero
#define BM    128
#define BN    128
#define BK    64
#define NCHUNK 72
#define STAGE_BYTES 32768  // A 16K + B 16K (fp16)
#define NSTAGE 3

// ---------------- device scratch ----------------
__device__ float g_sn[B_*CIN];
__device__ float g_bmod[B_*COUT];
__device__ float g_r[COUT];
__device__ float g_S2t[CIN*COUT];
__device__ float g_outscale[B_*COUT];
__device__ __half g_xt[(size_t)B_*QROWS*CIN];     // [b][q][i]
__device__ __half g_wa[4*NCHUNK*BM*BK];           // [ot][chunk][o][j]
__device__ float g_conv[(size_t)B_*COUT*NPIX];

// ---------------- PTX helpers ----------------
__device__ __forceinline__ uint32_t smem_u32(const void* p) {
    uint32_t a;
    asm("{ .reg .u64 t; cvta.to.shared.u64 t, %1; cvt.u32.u64 %0, t; }" : "=r"(a) : "l"(p));
    return a;
}
__device__ __forceinline__ void cp_async16(uint32_t dst, const void* src) {
    asm volatile("cp.async.cg.shared.global [%0], [%1], 16;" :: "r"(dst), "l"(src) : "memory");
}
__device__ __forceinline__ void ldsm4(uint32_t* r, uint32_t addr) {
    asm volatile("ldmatrix.sync.aligned.m8n8.x4.shared.b16 {%0,%1,%2,%3}, [%4];"
        : "=r"(r[0]), "=r"(r[1]), "=r"(r[2]), "=r"(r[3]) : "r"(addr));
}
__device__ __forceinline__ void mma16816(float* c, const uint32_t* a, const uint32_t* b) {
    asm volatile("mma.sync.aligned.m16n8k16.row.col.f32.f16.f16.f32 "
        "{%0,%1,%2,%3}, {%4,%5,%6,%7}, {%8,%9}, {%0,%1,%2,%3};"
        : "+f"(c[0]), "+f"(c[1]), "+f"(c[2]), "+f"(c[3])
        : "r"(a[0]), "r"(a[1]), "r"(a[2]), "r"(a[3]), "r"(b[0]), "r"(b[1]));
}

// ================= K0: styles / bias =================
__global__ void k_style(const float* __restrict__ w, const float* __restrict__ msg,
                        const float* __restrict__ aw, const float* __restrict__ ab,
                        const float* __restrict__ ms, const float* __restrict__ mb,
                        const float* __restrict__ bias)
{
    int b = blockIdx.x, i = threadIdx.x;
    __shared__ float sw[512], sm[64], red[512];
    sw[i] = w[b*512 + i];
    if (i < 64) sm[i] = msg[b*64 + i];
    __syncthreads();
    float acc = ab[i];
    const float4* awr = (const float4*)(aw + (size_t)i*512);
    #pragma unroll 4
    for (int j4 = 0; j4 < 128; j4++) {
        float4 a = awr[j4];
        acc += sw[4*j4+0]*a.x + sw[4*j4+1]*a.y + sw[4*j4+2]*a.z + sw[4*j4+3]*a.w;
    }
    float macc = 0.f;
    #pragma unroll 8
    for (int m = 0; m < 64; m++) macc += sm[m]*ms[m*512 + i];
    acc += 0.01f*macc;
    red[i] = acc*acc;
    __syncthreads();
    for (int s = 256; s > 0; s >>= 1) { if (i < s) red[i] += red[i+s]; __syncthreads(); }
    g_sn[b*512+i] = acc * rsqrtf(red[0]*(1.0f/512.0f));
    float bacc = 0.f;
    #pragma unroll 8
    for (int m = 0; m < 64; m++) bacc += sm[m]*mb[m*512 + i];
    g_bmod[b*512+i] = bias[i] + 0.01f*bacc;
}

// ================= K1: weight stats + fp16 GEMM-A tiles (fused) =================
__global__ void k_wstats(const float* __restrict__ weight)
{
    int o = blockIdx.x, tid = threadIdx.x;     // 256 threads
    int ot = o >> 7, ol = o & 127;
    __shared__ float red[256];
    float part = 0.f;
    for (int i = tid; i < 512; i += 256) {
        const float* wp = weight + ((size_t)o*512 + i)*9;
        float s2 = 0.f;
        int mh = i >> 6, j = i & 63;
        #pragma unroll
        for (int k = 0; k < 9; k++) {
            float v = wp[k];
            s2 += v*v;
            g_wa[((ot*NCHUNK + k*8 + mh)*128 + ol)*64 + j] = __float2half(v);
        }
        g_S2t[i*512 + o] = s2;
        part += s2;
    }
    red[tid] = part;
    __syncthreads();
    for (int s = 128; s > 0; s >>= 1) { if (tid < s) red[tid] += red[tid+s]; __syncthreads(); }
    if (tid == 0) g_r[o] = rsqrtf(red[0]*(1.0f/4608.0f));
}

// ================= K2: demod scale =================
__global__ void k_outscale(const float* __restrict__ ema)
{
    int b = blockIdx.y;
    int o = blockIdx.x*128 + threadIdx.x;
    __shared__ float ssn2[512];
    for (int i = threadIdx.x; i < 512; i += 128) { float v = g_sn[b*512+i]; ssn2[i] = v*v; }
    __syncthreads();
    float acc = 0.f;
    #pragma unroll 4
    for (int i = 0; i < 512; i++) acc += ssn2[i]*g_S2t[i*512 + o];
    float r = g_r[o];
    g_outscale[b*512+o] = r * rsqrtf(r*r*acc + 1e-8f) * rsqrtf(ema[0]);
}

// ================= K3: x transpose + style-scale + fp16 =================
__global__ void k_xprep(const float* __restrict__ x)
{
    __shared__ float s[32][33];
    int tx = threadIdx.x, ty = threadIdx.y;
    int q0 = blockIdx.x*32, i0 = blockIdx.y*32, b = blockIdx.z;
    #pragma unroll
    for (int k = 0; k < 4; k++) {
        int ii = ty + k*8;
        int i = i0 + ii;
        int q = q0 + tx;
        int r = q/40, c = q%40;
        float v = 0.f;
        if (r >= 2 && r < 38 && c >= 2 && c < 38)
            v = x[((size_t)(b*512+i)*36 + (r-2))*36 + (c-2)];
        s[ii][tx] = v * g_sn[b*512+i];
    }
    __syncthreads();
    #pragma unroll
    for (int k = 0; k < 4; k++) {
        int qq = ty + k*8;
        int q = q0 + qq;
        g_xt[((size_t)b*QROWS + q)*512 + i0 + tx] = __float2half(s[tx][qq]);
    }
}

// ================= K5: mma.sync fp16 implicit-GEMM conv (3-stage, 2 CTA/SM) ==========
struct KG {
    uint32_t sb;
    int b, ot, q0, tid;
    __device__ __forceinline__ void issue(int i, int stage) {
        uint32_t stu = sb + (uint32_t)stage*STAGE_BYTES;
        int tap = i >> 3;
        int off = (tap/3)*40 + (tap%3);
        int i0c = (i & 7) * 64;
        const char* ga = (const char*)(g_wa + ((size_t)(ot*NCHUNK + i))*BM*BK);
        const char* gb = (const char*)(g_xt + ((size_t)b*QROWS + q0 + off)*512 + i0c);
        #pragma unroll
        for (int j = 0; j < 4; j++) {
            int e = tid + j*256;
            int row = e >> 3, ch = e & 7;
            uint32_t sw = (uint32_t)row*128 + (uint32_t)((ch ^ (row & 7)) << 4);
            cp_async16(stu + sw,          ga + row*128 + ch*16);
            cp_async16(stu + 16384 + sw,  gb + (size_t)row*1024 + ch*16);
        }
        asm volatile("cp.async.commit_group;" ::: "memory");
    }
};

__global__ void __launch_bounds__(256, 2) k_gemm()
{
    extern __shared__ char smem[];
    KG kg;
    kg.sb = smem_u32(smem);
    kg.b = blockIdx.z; kg.ot = blockIdx.y; kg.q0 = blockIdx.x * BN; kg.tid = threadIdx.x;
    const int lane = kg.tid & 31;
    const int wid = kg.tid >> 5;
    const int wm = wid & 3;
    const int wn = wid >> 2;

    float c[2][8][4];
    #pragma unroll
    for (int a = 0; a < 2; a++)
        #pragma unroll
        for (int bq = 0; bq < 8; bq++)
            #pragma unroll
            for (int k = 0; k < 4; k++) c[a][bq][k] = 0.f;

    kg.issue(0, 0);
    kg.issue(1, 1);

    int cstage = 0;
    for (int i = 0; i < NCHUNK; i++) {
        if (i < NCHUNK-1) asm volatile("cp.async.wait_group 1;" ::: "memory");
        else              asm volatile("cp.async.wait_group 0;" ::: "memory");
        __syncthreads();

        if (i + 2 < NCHUNK) {
            int ns = cstage + 2; if (ns >= NSTAGE) ns -= NSTAGE;
            kg.issue(i + 2, ns);
        }

        uint32_t sbase = kg.sb + (uint32_t)cstage*STAGE_BYTES;
        #pragma unroll
        for (int ks = 0; ks < 4; ks++) {
            uint32_t ah[2][4];
            #pragma unroll
            for (int mi = 0; mi < 2; mi++) {
                int row = wm*32 + mi*16 + (lane & 15);
                int ch  = ks*2 + (lane >> 4);
                uint32_t off = (uint32_t)row*128 + (uint32_t)((ch ^ (row & 7)) << 4);
                ldsm4(ah[mi], sbase + off);
            }
            uint32_t bh[4][4];
            #pragma unroll
            for (int ni = 0; ni < 4; ni++) {
                int row = wn*64 + ni*16 + (lane & 7) + ((lane >> 4) << 3);
                int ch  = ks*2 + ((lane >> 3) & 1);
                uint32_t off = (uint32_t)row*128 + (uint32_t)((ch ^ (row & 7)) << 4);
                ldsm4(bh[ni], sbase + 16384 + off);
            }
            #pragma unroll
            for (int mi = 0; mi < 2; mi++)
                #pragma unroll
                for (int ni = 0; ni < 4; ni++)
                    #pragma unroll
                    for (int half = 0; half < 2; half++)
                        mma16816(c[mi][ni*2+half], ah[mi], &bh[ni][half*2]);
        }
        cstage++; if (cstage >= NSTAGE) cstage = 0;
    }

    #pragma unroll
    for (int mi = 0; mi < 2; mi++) {
        int o0 = kg.ot*128 + wm*32 + mi*16 + (lane >> 2);
        float sc0 = g_outscale[kg.b*512 + o0],     bb0 = g_bmod[kg.b*512 + o0];
        float sc8 = g_outscale[kg.b*512 + o0 + 8], bb8 = g_bmod[kg.b*512 + o0 + 8];
        float* d0 = g_conv + ((size_t)(kg.b*512 + o0))*NPIX;
        float* d8 = g_conv + ((size_t)(kg.b*512 + o0 + 8))*NPIX;
        #pragma unroll
        for (int nb = 0; nb < 8; nb++) {
            int q = kg.q0 + wn*64 + nb*8 + 2*(lane & 3);
            int rr = q/40, cc = q - rr*40;
            if (rr < 38 && cc < 38) {
                int oi = rr*38 + cc;
                d0[oi]   = c[mi][nb][0]*sc0 + bb0;
                d0[oi+1] = c[mi][nb][1]*sc0 + bb0;
                d8[oi]   = c[mi][nb][2]*sc8 + bb8;
                d8[oi+1] = c[mi][nb][3]*sc8 + bb8;
            }
        }
    }
}

// ================= K6: fused filtered_lrelu (even/odd phase pairing) =================
// SMEM (floats, liveness-aliased):
//   t1p : [0, 3936)       82 x 48 (up-V out);  t2 overlays after P2
//   sinp: [3936, 5776)    46 x 40 (padded in); z overlays after P1
//   z   : [3936, 10906)   82 x 85 (stride 85 -> conflict-free u-major reads)
//   t2  : [0, 2952)       82 x 36
__global__ void k_fir(const float* __restrict__ fu, const float* __restrict__ fd,
                      float* __restrict__ out)
{
    int plane = blockIdx.x;
    const float* src = g_conv + (size_t)plane*NPIX;
    float* dst = out + (size_t)plane*NOUT;

    __shared__ float smem[10906];
    __shared__ float fuf[12], fdf[12];
    float* t1p  = smem;            // stride 48
    float* sinp = smem + 3936;     // stride 40
    float* z    = smem + 3936;     // stride 85
    float* t2   = smem;            // stride 36

    int tid = threadIdx.x;         // 256
    if (tid < 12) { fuf[tid] = fu[11 - tid]; fdf[tid] = fd[11 - tid]; }
    for (int e = tid; e < 46*40; e += 256) {
        int c = e % 40, r = e / 40;
        float v = 0.f;
        int rr = r - 4;
        if (rr >= 0 && rr < 38 && c < 38) v = src[rr*38 + c];
        sinp[e] = v;
    }
    __syncthreads();

    // P1: vertical up-FIR. Outputs u=2m and 2m+1 share source rows m..m+5.
    for (int e = tid; e < 41*46; e += 256) {
        int qc = e % 46, m = e / 46;
        int c = qc - 4;
        float ae = 0.f, ao = 0.f;
        if (c >= 0 && c < 38) {
            const float* sp = sinp + m*40 + c;
            #pragma unroll
            for (int s = 0; s < 6; s++) {
                float xv = sp[s*40];
                ae += fuf[1 + 2*s]*xv;    // u even (t0=1)
                ao += fuf[2*s]*xv;        // u odd  (t0=0)
            }
        }
        t1p[(2*m)*48 + qc]   = ae;
        t1p[(2*m+1)*48 + qc] = ao;
    }
    __syncthreads();

    // P2: horizontal up-FIR + gain + lrelu + clamp. v=2n,2n+1 share cols n..n+5.
    for (int e = tid; e < 82*41; e += 256) {
        int n = e % 41, u = e / 41;
        const float* tp = t1p + u*48 + n;
        float ae = 0.f, ao = 0.f;
        #pragma unroll
        for (int s = 0; s < 6; s++) {
            float xv = tp[s];
            ae += fuf[1 + 2*s]*xv;
            ao += fuf[2*s]*xv;
        }
        ae *= 4.0f; ae = (ae >= 0.f ? ae : 0.2f*ae) * 1.4142135623730951f;
        ae = fminf(fmaxf(ae, -256.f), 256.f);
        ao *= 4.0f; ao = (ao >= 0.f ? ao : 0.2f*ao) * 1.4142135623730951f;
        ao = fminf(fmaxf(ao, -256.f), 256.f);
        z[u*85 + 2*n]   = ae;
        z[u*85 + 2*n+1] = ao;
    }
    __syncthreads();

    // P3: horizontal down-FIR. Outputs w=2w2, 2w2+1 share 14-wide window.
    for (int e = tid; e < 82*18; e += 256) {
        int u = e % 82, w2 = e / 82;
        const float* zp = z + u*85 + 4*w2;
        float zz[14];
        #pragma unroll
        for (int t = 0; t < 14; t++) zz[t] = zp[t];
        float a0 = 0.f, a1 = 0.f;
        #pragma unroll
        for (int t = 0; t < 12; t++) { a0 += fdf[t]*zz[t]; a1 += fdf[t]*zz[t+2]; }
        t2[u*36 + 2*w2]   = a0;
        t2[u*36 + 2*w2+1] = a1;
    }
    __syncthreads();

    // P4: vertical down-FIR. Outputs h=2h2, 2h2+1 share 14-row window.
    for (int e = tid; e < 18*36; e += 256) {
        int w = e % 36, h2 = e / 36;
        const float* tp = t2 + 4*h2*36 + w;
        float tt[14];
        #pragma unroll
        for (int t = 0; t < 14; t++) tt[t] = tp[t*36];
        float a0 = 0.f, a1 = 0.f;
        #pragma unroll
        for (int t = 0; t < 12; t++) { a0 += fdf[t]*tt[t]; a1 += fdf[t]*tt[t+2]; }
        dst[(2*h2)*36 + w]   = a0;
        dst[(2*h2+1)*36 + w] = a1;
    }
}

// ================= launch =================
extern "C" void kernel_launch(void* const* d_in, const int* in_sizes, int n_in,
                              void* d_out, int out_size)
{
    const float* x    = (const float*)d_in[0];
    const float* w    = (const float*)d_in[1];
    const float* msg  = (const float*)d_in[2];
    const float* aw   = (const float*)d_in[3];
    const float* ab   = (const float*)d_in[4];
    const float* wt   = (const float*)d_in[5];
    const float* bias = (const float*)d_in[6];
    const float* ms   = (const float*)d_in[7];
    const float* mb   = (const float*)d_in[8];
    const float* fu   = (const float*)d_in[9];
    const float* fd   = (const float*)d_in[10];
    const float* ema  = (const float*)d_in[11];
    float* out = (float*)d_out;

    static bool attr_set = false;
    if (!attr_set) {
        cudaFuncSetAttribute(k_gemm, cudaFuncAttributeMaxDynamicSharedMemorySize, NSTAGE*STAGE_BYTES);
        attr_set = true;
    }

    k_style   <<<16, 512>>>(w, msg, aw, ab, ms, mb, bias);
    k_wstats  <<<512, 256>>>(wt);
    k_outscale<<<dim3(4,16), 128>>>(ema);
    k_xprep   <<<dim3(50,16,16), dim3(32,8)>>>(x);
    k_gemm    <<<dim3(12,4,16), 256, NSTAGE*STAGE_BYTES>>>();
    k_fir     <<<B_*COUT, 256>>>(fu, fd, out);
}

// round 7
// speedup vs baseline: 6.9827x; 1.0324x over previous
#include <cuda_runtime.h>
#include <cuda_fp16.h>
#include <cstdint>

// ---------------- problem constants ----------------
#define B_    16
#define CIN   512
#define COUT  512
#define HS    36
#define NPIX  (38*38)
#define NOUT  (36*36)
#define QROWS 1792
#define BM    128
#define BN    128
#define BK    64
#define NCHUNK 72
#define STAGE_BYTES 32768
#define NSTAGE 3

// ---------------- device scratch ----------------
__device__ float g_sn[B_*CIN];
__device__ float g_bmod[B_*COUT];
__device__ float g_r[COUT];
__device__ float g_S2t[CIN*COUT];
__device__ float g_outscale[B_*COUT];
__device__ __half g_xt[(size_t)B_*QROWS*CIN];
__device__ __half g_wa[4*NCHUNK*BM*BK];
__device__ float g_conv[(size_t)B_*COUT*NPIX];

// ---------------- PTX helpers ----------------
__device__ __forceinline__ uint32_t smem_u32(const void* p) {
    uint32_t a;
    asm("{ .reg .u64 t; cvta.to.shared.u64 t, %1; cvt.u32.u64 %0, t; }" : "=r"(a) : "l"(p));
    return a;
}
__device__ __forceinline__ void cp_async16(uint32_t dst, const void* src) {
    asm volatile("cp.async.cg.shared.global [%0], [%1], 16;" :: "r"(dst), "l"(src) : "memory");
}
__device__ __forceinline__ void ldsm4(uint32_t* r, uint32_t addr) {
    asm volatile("ldmatrix.sync.aligned.m8n8.x4.shared.b16 {%0,%1,%2,%3}, [%4];"
        : "=r"(r[0]), "=r"(r[1]), "=r"(r[2]), "=r"(r[3]) : "r"(addr));
}
__device__ __forceinline__ void mma16816(float* c, const uint32_t* a, const uint32_t* b) {
    asm volatile("mma.sync.aligned.m16n8k16.row.col.f32.f16.f16.f32 "
        "{%0,%1,%2,%3}, {%4,%5,%6,%7}, {%8,%9}, {%0,%1,%2,%3};"
        : "+f"(c[0]), "+f"(c[1]), "+f"(c[2]), "+f"(c[3])
        : "r"(a[0]), "r"(a[1]), "r"(a[2]), "r"(a[3]), "r"(b[0]), "r"(b[1]));
}

// ================= K0: styles/bias (blocks 0..15) + weight stats (blocks 16..527) ======
__global__ void k_prep0(const float* __restrict__ w, const float* __restrict__ msg,
                        const float* __restrict__ aw, const float* __restrict__ ab,
                        const float* __restrict__ ms, const float* __restrict__ mb,
                        const float* __restrict__ bias, const float* __restrict__ weight)
{
    __shared__ float sw[512], sm[64], red[512];
    int tid = threadIdx.x;                      // 512
    if (blockIdx.x < 16) {
        int b = blockIdx.x, i = tid;
        sw[i] = w[b*512 + i];
        if (i < 64) sm[i] = msg[b*64 + i];
        __syncthreads();
        float acc = ab[i];
        const float4* awr = (const float4*)(aw + (size_t)i*512);
        #pragma unroll 4
        for (int j4 = 0; j4 < 128; j4++) {
            float4 a = awr[j4];
            acc += sw[4*j4+0]*a.x + sw[4*j4+1]*a.y + sw[4*j4+2]*a.z + sw[4*j4+3]*a.w;
        }
        float macc = 0.f;
        #pragma unroll 8
        for (int m = 0; m < 64; m++) macc += sm[m]*ms[m*512 + i];
        acc += 0.01f*macc;
        red[i] = acc*acc;
        __syncthreads();
        for (int s = 256; s > 0; s >>= 1) { if (i < s) red[i] += red[i+s]; __syncthreads(); }
        g_sn[b*512+i] = acc * rsqrtf(red[0]*(1.0f/512.0f));
        float bacc = 0.f;
        #pragma unroll 8
        for (int m = 0; m < 64; m++) bacc += sm[m]*mb[m*512 + i];
        g_bmod[b*512+i] = bias[i] + 0.01f*bacc;
    } else {
        int o = blockIdx.x - 16;
        int ot = o >> 7, ol = o & 127;
        int i = tid;
        const float* wp = weight + ((size_t)o*512 + i)*9;
        float s2 = 0.f;
        int mh = i >> 6, j = i & 63;
        #pragma unroll
        for (int k = 0; k < 9; k++) {
            float v = wp[k];
            s2 += v*v;
            g_wa[((ot*NCHUNK + k*8 + mh)*128 + ol)*64 + j] = __float2half(v);
        }
        g_S2t[i*512 + o] = s2;
        red[i] = s2;
        __syncthreads();
        for (int s = 256; s > 0; s >>= 1) { if (i < s) red[i] += red[i+s]; __syncthreads(); }
        if (i == 0) g_r[o] = rsqrtf(red[0]*(1.0f/4608.0f));
    }
}

// ================= K2: demod scale =================
__global__ void k_outscale(const float* __restrict__ ema)
{
    int b = blockIdx.y;
    int o = blockIdx.x*128 + threadIdx.x;
    __shared__ float ssn2[512];
    for (int i = threadIdx.x; i < 512; i += 128) { float v = g_sn[b*512+i]; ssn2[i] = v*v; }
    __syncthreads();
    float acc = 0.f;
    #pragma unroll 4
    for (int i = 0; i < 512; i++) acc += ssn2[i]*g_S2t[i*512 + o];
    float r = g_r[o];
    g_outscale[b*512+o] = r * rsqrtf(r*r*acc + 1e-8f) * rsqrtf(ema[0]);
}

// ================= K3: x transpose + style-scale + fp16 =================
__global__ void k_xprep(const float* __restrict__ x)
{
    __shared__ float s[32][33];
    int tx = threadIdx.x, ty = threadIdx.y;
    int q0 = blockIdx.x*32, i0 = blockIdx.y*32, b = blockIdx.z;
    #pragma unroll
    for (int k = 0; k < 4; k++) {
        int ii = ty + k*8;
        int i = i0 + ii;
        int q = q0 + tx;
        int r = q/40, c = q%40;
        float v = 0.f;
        if (r >= 2 && r < 38 && c >= 2 && c < 38)
            v = x[((size_t)(b*512+i)*36 + (r-2))*36 + (c-2)];
        s[ii][tx] = v * g_sn[b*512+i];
    }
    __syncthreads();
    #pragma unroll
    for (int k = 0; k < 4; k++) {
        int qq = ty + k*8;
        int q = q0 + qq;
        g_xt[((size_t)b*QROWS + q)*512 + i0 + tx] = __float2half(s[tx][qq]);
    }
}

// ================= K5: mma.sync fp16 implicit-GEMM conv =================
struct KG {
    uint32_t sb;
    int b, ot, q0, tid;
    __device__ __forceinline__ void issue(int i, int stage) {
        uint32_t stu = sb + (uint32_t)stage*STAGE_BYTES;
        int tap = i >> 3;
        int off = (tap/3)*40 + (tap%3);
        int i0c = (i & 7) * 64;
        const char* ga = (const char*)(g_wa + ((size_t)(ot*NCHUNK + i))*BM*BK);
        const char* gb = (const char*)(g_xt + ((size_t)b*QROWS + q0 + off)*512 + i0c);
        #pragma unroll
        for (int j = 0; j < 4; j++) {
            int e = tid + j*256;
            int row = e >> 3, ch = e & 7;
            uint32_t sw = (uint32_t)row*128 + (uint32_t)((ch ^ (row & 7)) << 4);
            cp_async16(stu + sw,          ga + row*128 + ch*16);
            cp_async16(stu + 16384 + sw,  gb + (size_t)row*1024 + ch*16);
        }
        asm volatile("cp.async.commit_group;" ::: "memory");
    }
};

__global__ void __launch_bounds__(256, 2) k_gemm()
{
    extern __shared__ char smem[];
    KG kg;
    kg.sb = smem_u32(smem);
    kg.b = blockIdx.z; kg.ot = blockIdx.y; kg.q0 = blockIdx.x * BN; kg.tid = threadIdx.x;
    const int lane = kg.tid & 31;
    const int wid = kg.tid >> 5;
    const int wm = wid & 3;
    const int wn = wid >> 2;

    float c[2][8][4];
    #pragma unroll
    for (int a = 0; a < 2; a++)
        #pragma unroll
        for (int bq = 0; bq < 8; bq++)
            #pragma unroll
            for (int k = 0; k < 4; k++) c[a][bq][k] = 0.f;

    kg.issue(0, 0);
    kg.issue(1, 1);

    int cstage = 0;
    for (int i = 0; i < NCHUNK; i++) {
        if (i < NCHUNK-1) asm volatile("cp.async.wait_group 1;" ::: "memory");
        else              asm volatile("cp.async.wait_group 0;" ::: "memory");
        __syncthreads();

        if (i + 2 < NCHUNK) {
            int ns = cstage + 2; if (ns >= NSTAGE) ns -= NSTAGE;
            kg.issue(i + 2, ns);
        }

        uint32_t sbase = kg.sb + (uint32_t)cstage*STAGE_BYTES;
        #pragma unroll
        for (int ks = 0; ks < 4; ks++) {
            uint32_t ah[2][4];
            #pragma unroll
            for (int mi = 0; mi < 2; mi++) {
                int row = wm*32 + mi*16 + (lane & 15);
                int ch  = ks*2 + (lane >> 4);
                uint32_t off = (uint32_t)row*128 + (uint32_t)((ch ^ (row & 7)) << 4);
                ldsm4(ah[mi], sbase + off);
            }
            uint32_t bh[4][4];
            #pragma unroll
            for (int ni = 0; ni < 4; ni++) {
                int row = wn*64 + ni*16 + (lane & 7) + ((lane >> 4) << 3);
                int ch  = ks*2 + ((lane >> 3) & 1);
                uint32_t off = (uint32_t)row*128 + (uint32_t)((ch ^ (row & 7)) << 4);
                ldsm4(bh[ni], sbase + 16384 + off);
            }
            #pragma unroll
            for (int mi = 0; mi < 2; mi++)
                #pragma unroll
                for (int ni = 0; ni < 4; ni++)
                    #pragma unroll
                    for (int half = 0; half < 2; half++)
                        mma16816(c[mi][ni*2+half], ah[mi], &bh[ni][half*2]);
        }
        cstage++; if (cstage >= NSTAGE) cstage = 0;
    }

    // epilogue: scale + bias, float2 stores (oi always even -> 8B aligned)
    #pragma unroll
    for (int mi = 0; mi < 2; mi++) {
        int o0 = kg.ot*128 + wm*32 + mi*16 + (lane >> 2);
        float sc0 = g_outscale[kg.b*512 + o0],     bb0 = g_bmod[kg.b*512 + o0];
        float sc8 = g_outscale[kg.b*512 + o0 + 8], bb8 = g_bmod[kg.b*512 + o0 + 8];
        float* d0 = g_conv + ((size_t)(kg.b*512 + o0))*NPIX;
        float* d8 = g_conv + ((size_t)(kg.b*512 + o0 + 8))*NPIX;
        #pragma unroll
        for (int nb = 0; nb < 8; nb++) {
            int q = kg.q0 + wn*64 + nb*8 + 2*(lane & 3);
            int rr = q/40, cc = q - rr*40;
            if (rr < 38 && cc < 38) {
                int oi = rr*38 + cc;
                *(float2*)(d0 + oi) = make_float2(c[mi][nb][0]*sc0 + bb0, c[mi][nb][1]*sc0 + bb0);
                *(float2*)(d8 + oi) = make_float2(c[mi][nb][2]*sc8 + bb8, c[mi][nb][3]*sc8 + bb8);
            }
        }
    }
}

// ================= K6: fused filtered_lrelu (register-rolling windows) =================
// SMEM (floats, liveness-aliased):
//   t1p : [0, 4018)       82 x 49 (stride 49, gcd(49,32)=1)
//   sinp: [4018, 5858)    46 x 40; z overlays after P1
//   z   : [4018, 10988)   82 x 85 (stride 85)
//   t2  : [0, 3034)       82 x 37 (stride 37), overlays t1p after P2
__global__ void k_fir(const float* __restrict__ fu, const float* __restrict__ fd,
                      float* __restrict__ out)
{
    int plane = blockIdx.x;
    const float* src = g_conv + (size_t)plane*NPIX;
    float* dst = out + (size_t)plane*NOUT;

    __shared__ float smem[10988];
    __shared__ float fuf[12], fdf[12];
    float* t1p  = smem;            // stride 49
    float* sinp = smem + 4018;     // stride 40
    float* z    = smem + 4018;     // stride 85
    float* t2   = smem;            // stride 37

    int tid = threadIdx.x;         // 256
    if (tid < 12) { fuf[tid] = fu[11 - tid]; fdf[tid] = fd[11 - tid]; }
    for (int e = tid; e < 46*40; e += 256) {
        int c = e % 40, r = e / 40;
        float v = 0.f;
        int rr = r - 4;
        if (rr >= 0 && rr < 38 && c < 38) v = src[rr*38 + c];
        sinp[e] = v;
    }
    __syncthreads();

    // P1: vertical up-FIR, register-rolled along m. 46 qc x 5 m-segments = 230 threads.
    if (tid < 230) {
        int qc = tid % 46, seg = tid / 46;
        int m0  = (seg == 0) ? 0 : (1 + seg*8);
        int len = (seg == 0) ? 9 : 8;
        int c = qc - 4;
        if (c >= 0 && c < 38) {
            const float* sp = sinp + c;
            float w0 = sp[(m0+0)*40], w1 = sp[(m0+1)*40], w2 = sp[(m0+2)*40],
                  w3 = sp[(m0+3)*40], w4 = sp[(m0+4)*40];
            for (int mm = 0; mm < len; mm++) {
                float w5 = sp[(m0+mm+5)*40];
                float ae = fuf[1]*w0 + fuf[3]*w1 + fuf[5]*w2 + fuf[7]*w3 + fuf[9]*w4 + fuf[11]*w5;
                float ao = fuf[0]*w0 + fuf[2]*w1 + fuf[4]*w2 + fuf[6]*w3 + fuf[8]*w4 + fuf[10]*w5;
                int m = m0 + mm;
                t1p[(2*m)*49 + qc]   = ae;
                t1p[(2*m+1)*49 + qc] = ao;
                w0 = w1; w1 = w2; w2 = w3; w3 = w4; w4 = w5;
            }
        } else {
            for (int mm = 0; mm < len; mm++) {
                int m = m0 + mm;
                t1p[(2*m)*49 + qc]   = 0.f;
                t1p[(2*m+1)*49 + qc] = 0.f;
            }
        }
    }
    __syncthreads();

    // P2: horizontal up-FIR + act, register-rolled along n. 82 u x 3 n-segments = 246 threads.
    if (tid < 246) {
        int u = tid % 82, seg = tid / 82;
        int n0  = seg*14;
        int len = (seg == 2) ? 13 : 14;
        const float* row = t1p + u*49;
        float* zr = z + u*85;
        float w0 = row[n0+0], w1 = row[n0+1], w2 = row[n0+2], w3 = row[n0+3], w4 = row[n0+4];
        for (int nn = 0; nn < len; nn++) {
            float w5 = row[n0+nn+5];
            float ae = fuf[1]*w0 + fuf[3]*w1 + fuf[5]*w2 + fuf[7]*w3 + fuf[9]*w4 + fuf[11]*w5;
            float ao = fuf[0]*w0 + fuf[2]*w1 + fuf[4]*w2 + fuf[6]*w3 + fuf[8]*w4 + fuf[10]*w5;
            ae *= 4.0f; ae = (ae >= 0.f ? ae : 0.2f*ae) * 1.4142135623730951f;
            ae = fminf(fmaxf(ae, -256.f), 256.f);
            ao *= 4.0f; ao = (ao >= 0.f ? ao : 0.2f*ao) * 1.4142135623730951f;
            ao = fminf(fmaxf(ao, -256.f), 256.f);
            int n = n0 + nn;
            zr[2*n]   = ae;
            zr[2*n+1] = ao;
            w0 = w1; w1 = w2; w2 = w3; w3 = w4; w4 = w5;
        }
    }
    __syncthreads();

    // P3: horizontal down-FIR, paired outputs share 14-wide window.
    for (int e = tid; e < 82*18; e += 256) {
        int u = e % 82, w2i = e / 82;
        const float* zp = z + u*85 + 4*w2i;
        float zz[14];
        #pragma unroll
        for (int t = 0; t < 14; t++) zz[t] = zp[t];
        float a0 = 0.f, a1 = 0.f;
        #pragma unroll
        for (int t = 0; t < 12; t++) { a0 += fdf[t]*zz[t]; a1 += fdf[t]*zz[t+2]; }
        t2[u*37 + 2*w2i]   = a0;
        t2[u*37 + 2*w2i+1] = a1;
    }
    __syncthreads();

    // P4: vertical down-FIR, paired outputs share 14-row window.
    for (int e = tid; e < 18*36; e += 256) {
        int w = e % 36, h2 = e / 36;
        const float* tp = t2 + 4*h2*37 + w;
        float tt[14];
        #pragma unroll
        for (int t = 0; t < 14; t++) tt[t] = tp[t*37];
        float a0 = 0.f, a1 = 0.f;
        #pragma unroll
        for (int t = 0; t < 12; t++) { a0 += fdf[t]*tt[t]; a1 += fdf[t]*tt[t+2]; }
        dst[(2*h2)*36 + w]   = a0;
        dst[(2*h2+1)*36 + w] = a1;
    }
}

// ================= launch =================
extern "C" void kernel_launch(void* const* d_in, const int* in_sizes, int n_in,
                              void* d_out, int out_size)
{
    const float* x    = (const float*)d_in[0];
    const float* w    = (const float*)d_in[1];
    const float* msg  = (const float*)d_in[2];
    const float* aw   = (const float*)d_in[3];
    const float* ab   = (const float*)d_in[4];
    const float* wt   = (const float*)d_in[5];
    const float* bias = (const float*)d_in[6];
    const float* ms   = (const float*)d_in[7];
    const float* mb   = (const float*)d_in[8];
    const float* fu   = (const float*)d_in[9];
    const float* fd   = (const float*)d_in[10];
    const float* ema  = (const float*)d_in[11];
    float* out = (float*)d_out;

    static bool attr_set = false;
    if (!attr_set) {
        cudaFuncSetAttribute(k_gemm, cudaFuncAttributeMaxDynamicSharedMemorySize, NSTAGE*STAGE_BYTES);
        attr_set = true;
    }

    k_prep0   <<<528, 512>>>(w, msg, aw, ab, ms, mb, bias, wt);
    k_outscale<<<dim3(4,16), 128>>>(ema);
    k_xprep   <<<dim3(50,16,16), dim3(32,8)>>>(x);
    k_gemm    <<<dim3(12,4,16), 256, NSTAGE*STAGE_BYTES>>>();
    k_fir     <<<B_*COUT, 256>>>(fu, fd, out);
}